// round 12
// baseline (speedup 1.0000x reference)
#include <cuda_runtime.h>
#include <cuda_fp16.h>
#include <cstdint>

#define NN 50000
#define EE 600000

// ---------------- scratch ---------------------------------------------------
__device__ float  g_h  [(size_t)NN * 128];
__device__ __half g_hh [(size_t)NN * 128];   // fp16 shadow of h (12.8 MB)
__device__ float  g_agg[(size_t)NN * 128];
__device__ float  g_t  [(size_t)NN * 128];
__device__ __half g_ea [(size_t)EE * 128];   // fp16 edge features (154 MB)
// CSR scratch
__device__ int g_deg   [NN];
__device__ int g_start [NN + 1];
__device__ int g_cursor[NN];
__device__ int g_eidx  [EE];
__device__ int g_esrc  [EE];

// ---------------- helpers ----------------------------------------------------
// split (x0,x1) into packed bf16x2 hi and lo words: x ~= hi + lo, err ~2^-17
__device__ __forceinline__ void split2(float x0, float x1, uint32_t& hi, uint32_t& lo) {
    asm("cvt.rn.bf16x2.f32 %0, %2, %1;" : "=r"(hi) : "f"(x0), "f"(x1));
    float h0 = __uint_as_float(hi << 16);
    float h1 = __uint_as_float(hi & 0xffff0000u);
    float l0 = x0 - h0, l1 = x1 - h1;
    asm("cvt.rn.bf16x2.f32 %0, %2, %1;" : "=r"(lo) : "f"(l0), "f"(l1));
}
__device__ __forceinline__ void mma_bf16(float* d,
                                         uint32_t a0, uint32_t a1, uint32_t a2, uint32_t a3,
                                         uint32_t b0, uint32_t b1) {
    asm volatile("mma.sync.aligned.m16n8k16.row.col.f32.bf16.bf16.f32 "
        "{%0,%1,%2,%3}, {%4,%5,%6,%7}, {%8,%9}, {%0,%1,%2,%3};"
        : "+f"(d[0]), "+f"(d[1]), "+f"(d[2]), "+f"(d[3])
        : "r"(a0), "r"(a1), "r"(a2), "r"(a3), "r"(b0), "r"(b1));
}
__device__ __forceinline__ float wsum(float v) {
#pragma unroll
    for (int o = 16; o > 0; o >>= 1) v += __shfl_xor_sync(0xffffffffu, v, o);
    return v;
}

// SMEM word strides
#define KS2 68     // packed-k2 row stride

// word offsets inside dynamic smem (uint32 units); tile M = 64
#define OFF_AHI 0
#define OFF_ALO (64 * KS2)
#define OFF_BHI (2 * 64 * KS2)
#define OFF_BLO (2 * 64 * KS2 + 128 * KS2)
#define SMEM_WORDS (2 * 64 * KS2 + 2 * 128 * KS2)   // 26112 words = 104448 B

// ============================================================================
// Fused GEMM (out = f(A[rows,128] @ W[128,128])) via mma.sync bf16-split.
// Persistent CTAs; 64x128 tile per CTA; 8 warps; warp tile 32x32; 2 CTAs/SM.
// MODE 0: A = relu(x[KIN] @ w1 + b1) computed SIMT; epi: LN(D + b)
// MODE 1: A from gmem;                              epi: relu(D + b)
// MODE 2: A from gmem;                              epi: LN(hres + relu(D + b))
// OUTH 0: fp32 out1.  OUTH 1: fp16 only (out1 is __half*).  OUTH 2: fp32 + fp16.
// ============================================================================
template <int KIN, int MODE, int OUTH>
__global__ __launch_bounds__(256, 2)
void gemm128_kernel(const float* __restrict__ A, int rows,
                    const float* __restrict__ W, const float* __restrict__ bias,
                    const float* __restrict__ w1, const float* __restrict__ b1,
                    const float* __restrict__ gam, const float* __restrict__ bet,
                    const float* __restrict__ hres,
                    float* __restrict__ out1,
                    __half* __restrict__ outh)
{
    extern __shared__ uint32_t dyn[];
    uint32_t* Ahi = dyn + OFF_AHI;
    uint32_t* Alo = dyn + OFF_ALO;
    uint32_t* Bhi = dyn + OFF_BHI;
    uint32_t* Blo = dyn + OFF_BLO;
    __shared__ float w1s[KIN > 0 ? KIN * 128 : 1];
    __shared__ float b1s[128], bs[128], gs[128], bes[128];
    __shared__ float partial[64][9];   // [row][0..3]=sum per warp-col, [4..7]=sumsq

    const int tid  = threadIdx.x;
    const int lane = tid & 31;
    const int wrp  = tid >> 5;
    const int wm   = (wrp & 1) * 32;   // warp row offset (tile M=64)
    const int wn   = (wrp >> 1) * 32;  // warp col offset (4 groups)
    const int wc   = wn >> 5;          // warp-col index 0..3
    const int g    = lane >> 2;
    const int t4   = lane & 3;

    // ---- stage B = W (K-major) as packed bf16x2 hi/lo: Bs[n][k2] ----------
#pragma unroll
    for (int q = 0; q < 32; q++) {
        int i  = q * 256 + tid;
        int n  = i & 127, k2 = i >> 7;
        float v0 = W[(2 * k2) * 128 + n];
        float v1 = W[(2 * k2 + 1) * 128 + n];
        uint32_t h, l; split2(v0, v1, h, l);
        Bhi[n * KS2 + k2] = h;
        Blo[n * KS2 + k2] = l;
    }
    if (KIN > 0) {
        for (int i = tid; i < KIN * 128; i += 256) w1s[i] = w1[i];
        if (tid < 128) b1s[tid] = b1[tid];
    }
    if (tid < 128) {
        bs[tid] = bias[tid];
        if (MODE != 1) { gs[tid] = gam[tid]; bes[tid] = bet[tid]; }
    }
    __syncthreads();

    const int ntiles = (rows + 63) >> 6;
    for (int t = blockIdx.x; t < ntiles; t += gridDim.x) {
        const int row0 = t << 6;

        // ---------------- stage A tile (packed bf16x2 hi/lo) ----------------
        if (KIN > 0) {
            const int r = tid >> 2, p = tid & 3, rw = row0 + r;
            float xr[KIN > 0 ? KIN : 1];
#pragma unroll
            for (int j = 0; j < KIN; j++)
                xr[j] = (rw < rows) ? A[(size_t)rw * KIN + j] : 0.f;
#pragma unroll
            for (int j = 0; j < 16; j++) {
                int k2 = 4 * j + p;
                int c  = 2 * k2;
                float a0 = b1s[c], a1 = b1s[c + 1];
#pragma unroll
                for (int k = 0; k < KIN; k++) {
                    a0 = fmaf(xr[k], w1s[k * 128 + c], a0);
                    a1 = fmaf(xr[k], w1s[k * 128 + c + 1], a1);
                }
                a0 = fmaxf(a0, 0.f); a1 = fmaxf(a1, 0.f);
                uint32_t h, l; split2(a0, a1, h, l);
                Ahi[r * KS2 + k2] = h;
                Alo[r * KS2 + k2] = l;
            }
        } else {
#pragma unroll
            for (int q = 0; q < 16; q++) {
                int i  = q * 256 + tid;
                int r  = i >> 6, k2 = i & 63;
                float2 v = (row0 + r < rows)
                    ? *(const float2*)(A + (size_t)(row0 + r) * 128 + 2 * k2)
                    : make_float2(0.f, 0.f);
                uint32_t h, l; split2(v.x, v.y, h, l);
                Ahi[r * KS2 + k2] = h;
                Alo[r * KS2 + k2] = l;
            }
        }
        __syncthreads();

        // ---------------- mainloop: 8 k-steps (k=16 each), 3 bf16 terms ----
        float d[2][4][4];
#pragma unroll
        for (int mt = 0; mt < 2; mt++)
#pragma unroll
            for (int nt = 0; nt < 4; nt++)
#pragma unroll
                for (int i = 0; i < 4; i++) d[mt][nt][i] = 0.f;

#pragma unroll 1
        for (int ks = 0; ks < 8; ks++) {
            const int kb = ks * 8 + t4;
            uint32_t ah[2][4], al[2][4];
#pragma unroll
            for (int mt = 0; mt < 2; mt++) {
                const int rb = (wm + mt * 16 + g) * KS2 + kb;
                ah[mt][0] = Ahi[rb];
                ah[mt][1] = Ahi[rb + 8 * KS2];
                ah[mt][2] = Ahi[rb + 4];
                ah[mt][3] = Ahi[rb + 8 * KS2 + 4];
                al[mt][0] = Alo[rb];
                al[mt][1] = Alo[rb + 8 * KS2];
                al[mt][2] = Alo[rb + 4];
                al[mt][3] = Alo[rb + 8 * KS2 + 4];
            }
#pragma unroll
            for (int nt = 0; nt < 4; nt++) {
                const int nb = (wn + nt * 8 + g) * KS2 + kb;
                uint32_t bh0 = Bhi[nb], bh1 = Bhi[nb + 4];
                uint32_t bl0 = Blo[nb], bl1 = Blo[nb + 4];
#pragma unroll
                for (int mt = 0; mt < 2; mt++) {
                    mma_bf16(d[mt][nt], ah[mt][0], ah[mt][1], ah[mt][2], ah[mt][3], bh0, bh1);
                    mma_bf16(d[mt][nt], al[mt][0], al[mt][1], al[mt][2], al[mt][3], bh0, bh1);
                    mma_bf16(d[mt][nt], ah[mt][0], ah[mt][1], ah[mt][2], ah[mt][3], bl0, bl1);
                }
            }
        }

        // ---------------- epilogue: fragment-direct ----------------
        if (MODE == 1) {
#pragma unroll
            for (int mt = 0; mt < 2; mt++) {
#pragma unroll
                for (int h = 0; h < 2; h++) {
                    const int rl = wm + mt * 16 + g + 8 * h;
                    const int rw = row0 + rl;
                    if (rw < rows) {
#pragma unroll
                        for (int nt = 0; nt < 4; nt++) {
                            const int cb = wn + nt * 8 + 2 * t4;
                            float2 b = *(const float2*)&bs[cb];
                            float2 o;
                            o.x = fmaxf(d[mt][nt][2 * h]     + b.x, 0.f);
                            o.y = fmaxf(d[mt][nt][2 * h + 1] + b.y, 0.f);
                            *(float2*)(out1 + (size_t)rw * 128 + cb) = o;
                        }
                    }
                }
            }
        } else {
            // pass 1: bias(/relu/residual) in regs, per-row partial sums
#pragma unroll
            for (int mt = 0; mt < 2; mt++) {
#pragma unroll
                for (int h = 0; h < 2; h++) {
                    const int rl = wm + mt * 16 + g + 8 * h;
                    const int rw = row0 + rl;
                    const bool valid = rw < rows;
                    float sum = 0.f, sq = 0.f;
#pragma unroll
                    for (int nt = 0; nt < 4; nt++) {
                        const int cb = wn + nt * 8 + 2 * t4;
                        float2 b = *(const float2*)&bs[cb];
                        float w0 = d[mt][nt][2 * h]     + b.x;
                        float w1v = d[mt][nt][2 * h + 1] + b.y;
                        if (MODE == 2) {
                            float2 hv = valid ? *(const float2*)(hres + (size_t)rw * 128 + cb)
                                              : make_float2(0.f, 0.f);
                            w0  = hv.x + fmaxf(w0, 0.f);
                            w1v = hv.y + fmaxf(w1v, 0.f);
                        }
                        d[mt][nt][2 * h]     = w0;
                        d[mt][nt][2 * h + 1] = w1v;
                        sum += w0 + w1v;
                        sq  += w0 * w0 + w1v * w1v;
                    }
                    sum += __shfl_xor_sync(0xffffffffu, sum, 1);
                    sq  += __shfl_xor_sync(0xffffffffu, sq, 1);
                    sum += __shfl_xor_sync(0xffffffffu, sum, 2);
                    sq  += __shfl_xor_sync(0xffffffffu, sq, 2);
                    if (t4 == 0) {
                        partial[rl][wc]     = sum;
                        partial[rl][4 + wc] = sq;
                    }
                }
            }
            __syncthreads();
            // pass 2: combine 4 warp-col partials, normalize, store
#pragma unroll
            for (int mt = 0; mt < 2; mt++) {
#pragma unroll
                for (int h = 0; h < 2; h++) {
                    const int rl = wm + mt * 16 + g + 8 * h;
                    const int rw = row0 + rl;
                    float sum = partial[rl][0] + partial[rl][1] + partial[rl][2] + partial[rl][3];
                    float sq  = partial[rl][4] + partial[rl][5] + partial[rl][6] + partial[rl][7];
                    float mean = sum * 0.0078125f;
                    float var  = sq * 0.0078125f - mean * mean;
                    float inv  = rsqrtf(var + 1e-5f);
                    if (rw < rows) {
#pragma unroll
                        for (int nt = 0; nt < 4; nt++) {
                            const int cb = wn + nt * 8 + 2 * t4;
                            float2 gv = *(const float2*)&gs[cb];
                            float2 bv = *(const float2*)&bes[cb];
                            float ox = (d[mt][nt][2 * h]     - mean) * inv * gv.x + bv.x;
                            float oy = (d[mt][nt][2 * h + 1] - mean) * inv * gv.y + bv.y;
                            if (OUTH == 1) {
                                *(__half2*)((__half*)out1 + (size_t)rw * 128 + cb) =
                                    __floats2half2_rn(ox, oy);
                            } else {
                                *(float2*)(out1 + (size_t)rw * 128 + cb) = make_float2(ox, oy);
                                if (OUTH == 2)
                                    *(__half2*)(outh + (size_t)rw * 128 + cb) =
                                        __floats2half2_rn(ox, oy);
                            }
                        }
                    }
                }
            }
        }
        __syncthreads();  // smem (A region + partial) reused next tile
    }
}

// ============================================================================
// CSR build: zero -> histogram -> scan -> scatter
// ============================================================================
__global__ void zero_kernel(int* __restrict__ deg) {
    int i = blockIdx.x * blockDim.x + threadIdx.x;
    if (i < NN) deg[i] = 0;
}
__global__ void hist_kernel(const int* __restrict__ ei, int* __restrict__ deg) {
    int e = blockIdx.x * blockDim.x + threadIdx.x;
    if (e < EE) atomicAdd(&deg[ei[EE + e]], 1);
}
__global__ __launch_bounds__(1024, 1)
void scan_kernel(const int* __restrict__ deg, int* __restrict__ start,
                 int* __restrict__ cursor) {
    __shared__ int sums[1024];
    const int t = threadIdx.x;
    const int CH = (NN + 1023) / 1024;
    const int lo = t * CH;
    const int hi = (lo + CH < NN) ? lo + CH : NN;
    int s = 0;
    for (int i = lo; i < hi; i++) s += deg[i];
    sums[t] = s;
    __syncthreads();
    for (int o = 1; o < 1024; o <<= 1) {
        int u = (t >= o) ? sums[t - o] : 0;
        __syncthreads();
        sums[t] += u;
        __syncthreads();
    }
    int running = sums[t] - s;
    for (int i = lo; i < hi; i++) {
        start[i]  = running;
        cursor[i] = running;
        running += deg[i];
    }
    if (t == 1023) start[NN] = sums[1023];
}
__global__ void scatter_kernel(const int* __restrict__ ei, int* __restrict__ cursor,
                               int* __restrict__ eidx, int* __restrict__ esrc) {
    int e = blockIdx.x * blockDim.x + threadIdx.x;
    if (e >= EE) return;
    int dst = ei[EE + e];
    int pos = atomicAdd(&cursor[dst], 1);
    eidx[pos] = e;
    esrc[pos] = ei[e];
}

// ============================================================================
// Aggregation (gather): agg[n] = h[n] + sum_{e: dst=n} relu(hh[src_e] + ea[e])
// warp per (node, 64-feature half); lane covers float2. Neighbors in fp16.
// Unroll 8 with clamped-index predication (no latency-chained scalar tail).
// ============================================================================
__global__ __launch_bounds__(256, 4)
void gather_kernel(const int* __restrict__ start,
                   const int* __restrict__ eidx, const int* __restrict__ esrc,
                   const float* __restrict__ h, const __half* __restrict__ hh,
                   const __half* __restrict__ ea, float* __restrict__ agg)
{
    const int wg   = blockIdx.x * 8 + (threadIdx.x >> 5);
    const int lane = threadIdx.x & 31;
    const int node = wg >> 1;
    const int half = wg & 1;
    if (node >= NN) return;
    const int fo = half * 64 + lane * 2;       // feature offset (2 floats / lane)
    const int s   = __ldg(&start[node]);
    const int deg = __ldg(&start[node + 1]) - s;

    float2 acc = __ldg((const float2*)(h + (size_t)node * 128 + fo));

    for (int base = 0; base < deg; base += 32) {
        int rem = deg - base; if (rem > 32) rem = 32;
        int ie = 0, is_ = 0;
        if (lane < rem) {
            ie  = __ldg(&eidx[s + base + lane]);
            is_ = __ldg(&esrc[s + base + lane]);
        }
        for (int j = 0; j < rem; j += 8) {
            __half2 ev[8], hv[8];
#pragma unroll
            for (int u = 0; u < 8; u++) {
                int jj = (j + u < rem) ? j + u : j;   // clamp to a valid slot
                int e0 = __shfl_sync(0xffffffffu, ie,  jj);
                int s0 = __shfl_sync(0xffffffffu, is_, jj);
                ev[u] = __ldg((const __half2*)(ea + (size_t)e0 * 128 + fo));
                hv[u] = __ldg((const __half2*)(hh + (size_t)s0 * 128 + fo));
            }
#pragma unroll
            for (int u = 0; u < 8; u++) {
                if (j + u < rem) {
                    float2 e = __half22float2(ev[u]);
                    float2 v = __half22float2(hv[u]);
                    acc.x += fmaxf(v.x + e.x, 0.f);
                    acc.y += fmaxf(v.y + e.y, 0.f);
                }
            }
        }
    }
    *(float2*)(agg + (size_t)node * 128 + fo) = acc;
}

// ============================================================================
// Heads: one warp per node. Output: u[3N] | s[N] | log_s[N] | disp[1] | safety[N]
// ============================================================================
__global__ void heads_kernel(const float* __restrict__ h,
                             const float* __restrict__ dw1, const float* __restrict__ db1,
                             const float* __restrict__ dw2, const float* __restrict__ db2,
                             const float* __restrict__ sw1, const float* __restrict__ sb1,
                             const float* __restrict__ sw2, const float* __restrict__ sb2,
                             const float* __restrict__ lds,
                             float* __restrict__ out, int rows)
{
    __shared__ float hs[8][128];
    const int warp = threadIdx.x >> 5, lane = threadIdx.x & 31;
    const int node = blockIdx.x * 8 + warp;
    float disp = 0.001f + log1pf(expf(*lds));
    if (blockIdx.x == 0 && threadIdx.x == 0) out[5 * NN] = disp;
    if (node >= rows) return;

    float4 hv = ((const float4*)h)[(size_t)node * 32 + lane];
    ((float4*)hs[warp])[lane] = hv;
    __syncwarp();

    float d0 = db1[lane], d1 = db1[lane + 32];
    float s0 = sb1[lane], s1 = sb1[lane + 32];
#pragma unroll 4
    for (int k = 0; k < 128; k++) {
        float xv = hs[warp][k];
        d0 = fmaf(xv, __ldg(&dw1[k * 64 + lane]),      d0);
        d1 = fmaf(xv, __ldg(&dw1[k * 64 + lane + 32]), d1);
        s0 = fmaf(xv, __ldg(&sw1[k * 64 + lane]),      s0);
        s1 = fmaf(xv, __ldg(&sw1[k * 64 + lane + 32]), s1);
    }
    d0 = fmaxf(d0, 0.f); d1 = fmaxf(d1, 0.f);
    s0 = fmaxf(s0, 0.f); s1 = fmaxf(s1, 0.f);

    float p0 = d0 * dw2[lane * 3 + 0] + d1 * dw2[(lane + 32) * 3 + 0];
    float p1 = d0 * dw2[lane * 3 + 1] + d1 * dw2[(lane + 32) * 3 + 1];
    float p2 = d0 * dw2[lane * 3 + 2] + d1 * dw2[(lane + 32) * 3 + 2];
    float ps = s0 * sw2[lane] + s1 * sw2[lane + 32];
    p0 = wsum(p0); p1 = wsum(p1); p2 = wsum(p2); ps = wsum(ps);

    if (lane == 0) {
        float ls = ps + sb2[0];
        ls = fminf(fmaxf(ls, 0.f), 30.f);
        float s = expf(ls);
        out[node * 3 + 0] = (p0 + db2[0]) * disp;
        out[node * 3 + 1] = (p1 + db2[1]) * disp;
        out[node * 3 + 2] = (p2 + db2[2]) * disp;
        out[3 * NN + node] = s;
        out[4 * NN + node] = ls;
        out[5 * NN + 1 + node] = 2.5e8f / (s + 1e-8f);
    }
}

// ============================================================================
extern "C" void kernel_launch(void* const* d_in, const int* in_sizes, int n_in,
                              void* d_out, int out_size)
{
    const float* x     = (const float*)d_in[0];
    const float* eattr = (const float*)d_in[1];
    const int*   ei    = (const int*)  d_in[2];
    const float* ne_w1 = (const float*)d_in[3];
    const float* ne_b1 = (const float*)d_in[4];
    const float* ne_w2 = (const float*)d_in[5];
    const float* ne_b2 = (const float*)d_in[6];
    const float* ne_g  = (const float*)d_in[7];
    const float* ne_be = (const float*)d_in[8];
    const float* ee_w1 = (const float*)d_in[9];
    const float* ee_b1 = (const float*)d_in[10];
    const float* ee_w2 = (const float*)d_in[11];
    const float* ee_b2 = (const float*)d_in[12];
    const float* ee_g  = (const float*)d_in[13];
    const float* ee_be = (const float*)d_in[14];
    const float* cw1   = (const float*)d_in[15];
    const float* cb1   = (const float*)d_in[16];
    const float* cw2   = (const float*)d_in[17];
    const float* cb2   = (const float*)d_in[18];
    const float* pn_g  = (const float*)d_in[19];
    const float* pn_be = (const float*)d_in[20];
    const float* dw1   = (const float*)d_in[21];
    const float* db1   = (const float*)d_in[22];
    const float* dw2   = (const float*)d_in[23];
    const float* db2   = (const float*)d_in[24];
    const float* sw1   = (const float*)d_in[25];
    const float* sb1   = (const float*)d_in[26];
    const float* sw2   = (const float*)d_in[27];
    const float* sb2   = (const float*)d_in[28];
    const float* ldsc  = (const float*)d_in[29];
    float* out = (float*)d_out;

    void *ph, *phh, *pa, *pt, *pe, *pd, *ps, *pc, *px, *py;
    cudaGetSymbolAddress(&ph,  g_h);
    cudaGetSymbolAddress(&phh, g_hh);
    cudaGetSymbolAddress(&pa,  g_agg);
    cudaGetSymbolAddress(&pt,  g_t);
    cudaGetSymbolAddress(&pe,  g_ea);
    cudaGetSymbolAddress(&pd,  g_deg);
    cudaGetSymbolAddress(&ps,  g_start);
    cudaGetSymbolAddress(&pc,  g_cursor);
    cudaGetSymbolAddress(&px,  g_eidx);
    cudaGetSymbolAddress(&py,  g_esrc);
    float*  hbuf = (float*)ph;
    __half* hhb  = (__half*)phh;
    float*  abuf = (float*)pa;
    float*  tbuf = (float*)pt;
    __half* ebuf = (__half*)pe;
    int* deg    = (int*)pd;
    int* startb = (int*)ps;
    int* cursor = (int*)pc;
    int* eidx   = (int*)px;
    int* esrc   = (int*)py;

    const int gsm = SMEM_WORDS * 4;   // 104448 bytes
    cudaFuncSetAttribute(gemm128_kernel<5, 0, 2>, cudaFuncAttributeMaxDynamicSharedMemorySize, gsm);
    cudaFuncSetAttribute(gemm128_kernel<6, 0, 1>, cudaFuncAttributeMaxDynamicSharedMemorySize, gsm);
    cudaFuncSetAttribute(gemm128_kernel<0, 1, 0>, cudaFuncAttributeMaxDynamicSharedMemorySize, gsm);
    cudaFuncSetAttribute(gemm128_kernel<0, 2, 2>, cudaFuncAttributeMaxDynamicSharedMemorySize, gsm);

    // ---- CSR build (launches 1-3), then edge encoder as launch #4 (profiled)
    zero_kernel<<<(NN + 255) / 256, 256>>>(deg);
    hist_kernel<<<(EE + 255) / 256, 256>>>(ei, deg);
    scan_kernel<<<1, 1024>>>(deg, startb, cursor);

    // edge encoder: ea = fp16(LN(mlp2(edge_attr)))   [launch #4 -> ncu capture]
    gemm128_kernel<6, 0, 1><<<296, 256, gsm>>>(eattr, EE, ee_w2, ee_b2, ee_w1, ee_b1,
                                               ee_g, ee_be, nullptr, (float*)ebuf, nullptr);
    // node encoder: h = LN(mlp2(x)), hh = fp16(h)
    gemm128_kernel<5, 0, 2><<<296, 256, gsm>>>(x, NN, ne_w2, ne_b2, ne_w1, ne_b1,
                                               ne_g, ne_be, nullptr, hbuf, hhb);
    scatter_kernel<<<(EE + 255) / 256, 256>>>(ei, cursor, eidx, esrc);

    for (int l = 0; l < 3; l++) {
        gather_kernel<<<(2 * NN + 7) / 8, 256>>>(startb, eidx, esrc, hbuf, hhb, ebuf, abuf);
        // t = relu(agg @ w1 + b1)
        gemm128_kernel<0, 1, 0><<<296, 256, gsm>>>(abuf, NN, cw1 + (size_t)l * 16384, cb1 + l * 128,
                                                   nullptr, nullptr, nullptr, nullptr, nullptr,
                                                   tbuf, nullptr);
        // h = LN(h + relu(t @ w2 + b2)), hh = fp16(h)
        gemm128_kernel<0, 2, 2><<<296, 256, gsm>>>(tbuf, NN, cw2 + (size_t)l * 16384, cb2 + l * 128,
                                                   nullptr, nullptr, pn_g + l * 128, pn_be + l * 128,
                                                   hbuf, hbuf, hhb);
    }
    heads_kernel<<<(NN + 7) / 8, 256>>>(hbuf, dw1, db1, dw2, db2,
                                        sw1, sb1, sw2, sb2, ldsc, out, NN);
}

// round 13
// speedup vs baseline: 1.0893x; 1.0893x over previous
#include <cuda_runtime.h>
#include <cuda_fp16.h>
#include <cstdint>

#define NN 50000
#define EE 600000

// ---------------- scratch ---------------------------------------------------
__device__ float  g_h  [(size_t)NN * 128];
__device__ __half g_hh [(size_t)NN * 128];   // fp16 shadow of h (12.8 MB)
__device__ float  g_agg[(size_t)NN * 128];
__device__ float  g_t  [(size_t)NN * 128];
__device__ __half g_ea [(size_t)EE * 128];   // fp16 edge features (154 MB)
// CSR scratch
__device__ int g_deg   [NN];
__device__ int g_start [NN + 1];
__device__ int g_cursor[NN];
__device__ int g_eidx  [EE];
__device__ int g_esrc  [EE];

// ---------------- helpers ----------------------------------------------------
// split (x0,x1) into packed bf16x2 hi and lo words: x ~= hi + lo, err ~2^-17
__device__ __forceinline__ void split2(float x0, float x1, uint32_t& hi, uint32_t& lo) {
    asm("cvt.rn.bf16x2.f32 %0, %2, %1;" : "=r"(hi) : "f"(x0), "f"(x1));
    float h0 = __uint_as_float(hi << 16);
    float h1 = __uint_as_float(hi & 0xffff0000u);
    float l0 = x0 - h0, l1 = x1 - h1;
    asm("cvt.rn.bf16x2.f32 %0, %2, %1;" : "=r"(lo) : "f"(l0), "f"(l1));
}
__device__ __forceinline__ void mma_bf16(float* d,
                                         uint32_t a0, uint32_t a1, uint32_t a2, uint32_t a3,
                                         uint32_t b0, uint32_t b1) {
    asm volatile("mma.sync.aligned.m16n8k16.row.col.f32.bf16.bf16.f32 "
        "{%0,%1,%2,%3}, {%4,%5,%6,%7}, {%8,%9}, {%0,%1,%2,%3};"
        : "+f"(d[0]), "+f"(d[1]), "+f"(d[2]), "+f"(d[3])
        : "r"(a0), "r"(a1), "r"(a2), "r"(a3), "r"(b0), "r"(b1));
}
__device__ __forceinline__ float wsum(float v) {
#pragma unroll
    for (int o = 16; o > 0; o >>= 1) v += __shfl_xor_sync(0xffffffffu, v, o);
    return v;
}
// load 4 consecutive fp16 (8 B) -> float4
__device__ __forceinline__ float4 ld_h4(const __half* p) {
    uint2 u = __ldg((const uint2*)p);
    __half2 h0 = *reinterpret_cast<__half2*>(&u.x);
    __half2 h1 = *reinterpret_cast<__half2*>(&u.y);
    float2 f0 = __half22float2(h0);
    float2 f1 = __half22float2(h1);
    return make_float4(f0.x, f0.y, f1.x, f1.y);
}

// SMEM word strides
#define KS2 68     // packed-k2 row stride

// word offsets inside dynamic smem (uint32 units); tile M = 64
#define OFF_AHI 0
#define OFF_ALO (64 * KS2)
#define OFF_BHI (2 * 64 * KS2)
#define OFF_BLO (2 * 64 * KS2 + 128 * KS2)
#define SMEM_WORDS (2 * 64 * KS2 + 2 * 128 * KS2)   // 26112 words = 104448 B

// ============================================================================
// Fused GEMM (out = f(A[rows,128] @ W[128,128])) via mma.sync bf16-split.
// Persistent CTAs; 64x128 tile per CTA; 8 warps; warp tile 32x32; 2 CTAs/SM.
// MODE 0: A = relu(x[KIN] @ w1 + b1) computed SIMT; epi: LN(D + b)
// MODE 1: A from gmem;                              epi: relu(D + b)
// MODE 2: A from gmem;                              epi: LN(hres + relu(D + b))
// OUTH 0: fp32 out1.  OUTH 1: fp16 only (out1 is __half*).  OUTH 2: fp32 + fp16.
// ============================================================================
template <int KIN, int MODE, int OUTH>
__global__ __launch_bounds__(256, 2)
void gemm128_kernel(const float* __restrict__ A, int rows,
                    const float* __restrict__ W, const float* __restrict__ bias,
                    const float* __restrict__ w1, const float* __restrict__ b1,
                    const float* __restrict__ gam, const float* __restrict__ bet,
                    const float* __restrict__ hres,
                    float* __restrict__ out1,
                    __half* __restrict__ outh)
{
    extern __shared__ uint32_t dyn[];
    uint32_t* Ahi = dyn + OFF_AHI;
    uint32_t* Alo = dyn + OFF_ALO;
    uint32_t* Bhi = dyn + OFF_BHI;
    uint32_t* Blo = dyn + OFF_BLO;
    __shared__ float w1s[KIN > 0 ? KIN * 128 : 1];
    __shared__ float b1s[128], bs[128], gs[128], bes[128];
    __shared__ float partial[64][9];   // [row][0..3]=sum per warp-col, [4..7]=sumsq

    const int tid  = threadIdx.x;
    const int lane = tid & 31;
    const int wrp  = tid >> 5;
    const int wm   = (wrp & 1) * 32;   // warp row offset (tile M=64)
    const int wn   = (wrp >> 1) * 32;  // warp col offset (4 groups)
    const int wc   = wn >> 5;          // warp-col index 0..3
    const int g    = lane >> 2;
    const int t4   = lane & 3;

    // ---- stage B = W (K-major) as packed bf16x2 hi/lo: Bs[n][k2] ----------
#pragma unroll
    for (int q = 0; q < 32; q++) {
        int i  = q * 256 + tid;
        int n  = i & 127, k2 = i >> 7;
        float v0 = W[(2 * k2) * 128 + n];
        float v1 = W[(2 * k2 + 1) * 128 + n];
        uint32_t h, l; split2(v0, v1, h, l);
        Bhi[n * KS2 + k2] = h;
        Blo[n * KS2 + k2] = l;
    }
    if (KIN > 0) {
        for (int i = tid; i < KIN * 128; i += 256) w1s[i] = w1[i];
        if (tid < 128) b1s[tid] = b1[tid];
    }
    if (tid < 128) {
        bs[tid] = bias[tid];
        if (MODE != 1) { gs[tid] = gam[tid]; bes[tid] = bet[tid]; }
    }
    __syncthreads();

    const int ntiles = (rows + 63) >> 6;
    for (int t = blockIdx.x; t < ntiles; t += gridDim.x) {
        const int row0 = t << 6;

        // ---------------- stage A tile (packed bf16x2 hi/lo) ----------------
        if (KIN > 0) {
            const int r = tid >> 2, p = tid & 3, rw = row0 + r;
            float xr[KIN > 0 ? KIN : 1];
#pragma unroll
            for (int j = 0; j < KIN; j++)
                xr[j] = (rw < rows) ? A[(size_t)rw * KIN + j] : 0.f;
#pragma unroll
            for (int j = 0; j < 16; j++) {
                int k2 = 4 * j + p;
                int c  = 2 * k2;
                float a0 = b1s[c], a1 = b1s[c + 1];
#pragma unroll
                for (int k = 0; k < KIN; k++) {
                    a0 = fmaf(xr[k], w1s[k * 128 + c], a0);
                    a1 = fmaf(xr[k], w1s[k * 128 + c + 1], a1);
                }
                a0 = fmaxf(a0, 0.f); a1 = fmaxf(a1, 0.f);
                uint32_t h, l; split2(a0, a1, h, l);
                Ahi[r * KS2 + k2] = h;
                Alo[r * KS2 + k2] = l;
            }
        } else {
#pragma unroll
            for (int q = 0; q < 16; q++) {
                int i  = q * 256 + tid;
                int r  = i >> 6, k2 = i & 63;
                float2 v = (row0 + r < rows)
                    ? *(const float2*)(A + (size_t)(row0 + r) * 128 + 2 * k2)
                    : make_float2(0.f, 0.f);
                uint32_t h, l; split2(v.x, v.y, h, l);
                Ahi[r * KS2 + k2] = h;
                Alo[r * KS2 + k2] = l;
            }
        }
        __syncthreads();

        // ---------------- mainloop: 8 k-steps (k=16 each), 3 bf16 terms ----
        float d[2][4][4];
#pragma unroll
        for (int mt = 0; mt < 2; mt++)
#pragma unroll
            for (int nt = 0; nt < 4; nt++)
#pragma unroll
                for (int i = 0; i < 4; i++) d[mt][nt][i] = 0.f;

#pragma unroll 1
        for (int ks = 0; ks < 8; ks++) {
            const int kb = ks * 8 + t4;
            uint32_t ah[2][4], al[2][4];
#pragma unroll
            for (int mt = 0; mt < 2; mt++) {
                const int rb = (wm + mt * 16 + g) * KS2 + kb;
                ah[mt][0] = Ahi[rb];
                ah[mt][1] = Ahi[rb + 8 * KS2];
                ah[mt][2] = Ahi[rb + 4];
                ah[mt][3] = Ahi[rb + 8 * KS2 + 4];
                al[mt][0] = Alo[rb];
                al[mt][1] = Alo[rb + 8 * KS2];
                al[mt][2] = Alo[rb + 4];
                al[mt][3] = Alo[rb + 8 * KS2 + 4];
            }
#pragma unroll
            for (int nt = 0; nt < 4; nt++) {
                const int nb = (wn + nt * 8 + g) * KS2 + kb;
                uint32_t bh0 = Bhi[nb], bh1 = Bhi[nb + 4];
                uint32_t bl0 = Blo[nb], bl1 = Blo[nb + 4];
#pragma unroll
                for (int mt = 0; mt < 2; mt++) {
                    mma_bf16(d[mt][nt], ah[mt][0], ah[mt][1], ah[mt][2], ah[mt][3], bh0, bh1);
                    mma_bf16(d[mt][nt], al[mt][0], al[mt][1], al[mt][2], al[mt][3], bh0, bh1);
                    mma_bf16(d[mt][nt], ah[mt][0], ah[mt][1], ah[mt][2], ah[mt][3], bl0, bl1);
                }
            }
        }

        // ---------------- epilogue: fragment-direct ----------------
        if (MODE == 1) {
#pragma unroll
            for (int mt = 0; mt < 2; mt++) {
#pragma unroll
                for (int h = 0; h < 2; h++) {
                    const int rl = wm + mt * 16 + g + 8 * h;
                    const int rw = row0 + rl;
                    if (rw < rows) {
#pragma unroll
                        for (int nt = 0; nt < 4; nt++) {
                            const int cb = wn + nt * 8 + 2 * t4;
                            float2 b = *(const float2*)&bs[cb];
                            float2 o;
                            o.x = fmaxf(d[mt][nt][2 * h]     + b.x, 0.f);
                            o.y = fmaxf(d[mt][nt][2 * h + 1] + b.y, 0.f);
                            *(float2*)(out1 + (size_t)rw * 128 + cb) = o;
                        }
                    }
                }
            }
        } else {
            // pass 1: bias(/relu/residual) in regs, per-row partial sums
#pragma unroll
            for (int mt = 0; mt < 2; mt++) {
#pragma unroll
                for (int h = 0; h < 2; h++) {
                    const int rl = wm + mt * 16 + g + 8 * h;
                    const int rw = row0 + rl;
                    const bool valid = rw < rows;
                    float sum = 0.f, sq = 0.f;
#pragma unroll
                    for (int nt = 0; nt < 4; nt++) {
                        const int cb = wn + nt * 8 + 2 * t4;
                        float2 b = *(const float2*)&bs[cb];
                        float w0 = d[mt][nt][2 * h]     + b.x;
                        float w1v = d[mt][nt][2 * h + 1] + b.y;
                        if (MODE == 2) {
                            float2 hv = valid ? *(const float2*)(hres + (size_t)rw * 128 + cb)
                                              : make_float2(0.f, 0.f);
                            w0  = hv.x + fmaxf(w0, 0.f);
                            w1v = hv.y + fmaxf(w1v, 0.f);
                        }
                        d[mt][nt][2 * h]     = w0;
                        d[mt][nt][2 * h + 1] = w1v;
                        sum += w0 + w1v;
                        sq  += w0 * w0 + w1v * w1v;
                    }
                    sum += __shfl_xor_sync(0xffffffffu, sum, 1);
                    sq  += __shfl_xor_sync(0xffffffffu, sq, 1);
                    sum += __shfl_xor_sync(0xffffffffu, sum, 2);
                    sq  += __shfl_xor_sync(0xffffffffu, sq, 2);
                    if (t4 == 0) {
                        partial[rl][wc]     = sum;
                        partial[rl][4 + wc] = sq;
                    }
                }
            }
            __syncthreads();
            // pass 2: combine 4 warp-col partials, normalize, store
#pragma unroll
            for (int mt = 0; mt < 2; mt++) {
#pragma unroll
                for (int h = 0; h < 2; h++) {
                    const int rl = wm + mt * 16 + g + 8 * h;
                    const int rw = row0 + rl;
                    float sum = partial[rl][0] + partial[rl][1] + partial[rl][2] + partial[rl][3];
                    float sq  = partial[rl][4] + partial[rl][5] + partial[rl][6] + partial[rl][7];
                    float mean = sum * 0.0078125f;
                    float var  = sq * 0.0078125f - mean * mean;
                    float inv  = rsqrtf(var + 1e-5f);
                    if (rw < rows) {
#pragma unroll
                        for (int nt = 0; nt < 4; nt++) {
                            const int cb = wn + nt * 8 + 2 * t4;
                            float2 gv = *(const float2*)&gs[cb];
                            float2 bv = *(const float2*)&bes[cb];
                            float ox = (d[mt][nt][2 * h]     - mean) * inv * gv.x + bv.x;
                            float oy = (d[mt][nt][2 * h + 1] - mean) * inv * gv.y + bv.y;
                            if (OUTH == 1) {
                                *(__half2*)((__half*)out1 + (size_t)rw * 128 + cb) =
                                    __floats2half2_rn(ox, oy);
                            } else {
                                *(float2*)(out1 + (size_t)rw * 128 + cb) = make_float2(ox, oy);
                                if (OUTH == 2)
                                    *(__half2*)(outh + (size_t)rw * 128 + cb) =
                                        __floats2half2_rn(ox, oy);
                            }
                        }
                    }
                }
            }
        }
        __syncthreads();  // smem (A region + partial) reused next tile
    }
}

// ============================================================================
// CSR build: zero -> histogram -> scan -> scatter
// ============================================================================
__global__ void zero_kernel(int* __restrict__ deg) {
    int i = blockIdx.x * blockDim.x + threadIdx.x;
    if (i < NN) deg[i] = 0;
}
__global__ void hist_kernel(const int* __restrict__ ei, int* __restrict__ deg) {
    int e = blockIdx.x * blockDim.x + threadIdx.x;
    if (e < EE) atomicAdd(&deg[ei[EE + e]], 1);
}
__global__ __launch_bounds__(1024, 1)
void scan_kernel(const int* __restrict__ deg, int* __restrict__ start,
                 int* __restrict__ cursor) {
    __shared__ int sums[1024];
    const int t = threadIdx.x;
    const int CH = (NN + 1023) / 1024;
    const int lo = t * CH;
    const int hi = (lo + CH < NN) ? lo + CH : NN;
    int s = 0;
    for (int i = lo; i < hi; i++) s += deg[i];
    sums[t] = s;
    __syncthreads();
    for (int o = 1; o < 1024; o <<= 1) {
        int u = (t >= o) ? sums[t - o] : 0;
        __syncthreads();
        sums[t] += u;
        __syncthreads();
    }
    int running = sums[t] - s;
    for (int i = lo; i < hi; i++) {
        start[i]  = running;
        cursor[i] = running;
        running += deg[i];
    }
    if (t == 1023) start[NN] = sums[1023];
}
__global__ void scatter_kernel(const int* __restrict__ ei, int* __restrict__ cursor,
                               int* __restrict__ eidx, int* __restrict__ esrc) {
    int e = blockIdx.x * blockDim.x + threadIdx.x;
    if (e >= EE) return;
    int dst = ei[EE + e];
    int pos = atomicAdd(&cursor[dst], 1);
    eidx[pos] = e;
    esrc[pos] = ei[e];
}

// ============================================================================
// Aggregation (gather): agg[n] = h[n] + sum_{e: dst=n} relu(hh[src_e] + ea[e])
// warp per node, lane = 4-feature chunk (8B fp16 loads); R10 structure with
// lane-parallel index fetch + shfl, unroll 4. Only change vs R10/R11: h[src]
// read from fp16 shadow hh.
// ============================================================================
__global__ __launch_bounds__(256, 4)
void gather_kernel(const int* __restrict__ start,
                   const int* __restrict__ eidx, const int* __restrict__ esrc,
                   const float* __restrict__ h, const __half* __restrict__ hh,
                   const __half* __restrict__ ea, float* __restrict__ agg)
{
    const int warp = threadIdx.x >> 5, lane = threadIdx.x & 31;
    const int node = blockIdx.x * 8 + warp;
    if (node >= NN) return;
    const int s   = __ldg(&start[node]);
    const int deg = __ldg(&start[node + 1]) - s;

    float4 acc = __ldg((const float4*)h + (size_t)node * 32 + lane);

    for (int base = 0; base < deg; base += 32) {
        int rem = deg - base; if (rem > 32) rem = 32;
        int ie = 0, is_ = 0;
        if (lane < rem) {
            ie  = __ldg(&eidx[s + base + lane]);
            is_ = __ldg(&esrc[s + base + lane]);
        }
        int j = 0;
        for (; j + 4 <= rem; j += 4) {
            int e0 = __shfl_sync(0xffffffffu, ie, j);
            int e1 = __shfl_sync(0xffffffffu, ie, j + 1);
            int e2 = __shfl_sync(0xffffffffu, ie, j + 2);
            int e3 = __shfl_sync(0xffffffffu, ie, j + 3);
            int s0 = __shfl_sync(0xffffffffu, is_, j);
            int s1 = __shfl_sync(0xffffffffu, is_, j + 1);
            int s2 = __shfl_sync(0xffffffffu, is_, j + 2);
            int s3 = __shfl_sync(0xffffffffu, is_, j + 3);
            float4 ev0 = ld_h4(ea + (size_t)e0 * 128 + lane * 4);
            float4 ev1 = ld_h4(ea + (size_t)e1 * 128 + lane * 4);
            float4 ev2 = ld_h4(ea + (size_t)e2 * 128 + lane * 4);
            float4 ev3 = ld_h4(ea + (size_t)e3 * 128 + lane * 4);
            float4 hv0 = ld_h4(hh + (size_t)s0 * 128 + lane * 4);
            float4 hv1 = ld_h4(hh + (size_t)s1 * 128 + lane * 4);
            float4 hv2 = ld_h4(hh + (size_t)s2 * 128 + lane * 4);
            float4 hv3 = ld_h4(hh + (size_t)s3 * 128 + lane * 4);
            acc.x += fmaxf(hv0.x + ev0.x, 0.f) + fmaxf(hv1.x + ev1.x, 0.f)
                   + fmaxf(hv2.x + ev2.x, 0.f) + fmaxf(hv3.x + ev3.x, 0.f);
            acc.y += fmaxf(hv0.y + ev0.y, 0.f) + fmaxf(hv1.y + ev1.y, 0.f)
                   + fmaxf(hv2.y + ev2.y, 0.f) + fmaxf(hv3.y + ev3.y, 0.f);
            acc.z += fmaxf(hv0.z + ev0.z, 0.f) + fmaxf(hv1.z + ev1.z, 0.f)
                   + fmaxf(hv2.z + ev2.z, 0.f) + fmaxf(hv3.z + ev3.z, 0.f);
            acc.w += fmaxf(hv0.w + ev0.w, 0.f) + fmaxf(hv1.w + ev1.w, 0.f)
                   + fmaxf(hv2.w + ev2.w, 0.f) + fmaxf(hv3.w + ev3.w, 0.f);
        }
        for (; j < rem; j++) {
            int e0 = __shfl_sync(0xffffffffu, ie, j);
            int s0 = __shfl_sync(0xffffffffu, is_, j);
            float4 ev0 = ld_h4(ea + (size_t)e0 * 128 + lane * 4);
            float4 hv0 = ld_h4(hh + (size_t)s0 * 128 + lane * 4);
            acc.x += fmaxf(hv0.x + ev0.x, 0.f);
            acc.y += fmaxf(hv0.y + ev0.y, 0.f);
            acc.z += fmaxf(hv0.z + ev0.z, 0.f);
            acc.w += fmaxf(hv0.w + ev0.w, 0.f);
        }
    }
    ((float4*)agg)[(size_t)node * 32 + lane] = acc;
}

// ============================================================================
// Heads: one warp per node. Output: u[3N] | s[N] | log_s[N] | disp[1] | safety[N]
// ============================================================================
__global__ void heads_kernel(const float* __restrict__ h,
                             const float* __restrict__ dw1, const float* __restrict__ db1,
                             const float* __restrict__ dw2, const float* __restrict__ db2,
                             const float* __restrict__ sw1, const float* __restrict__ sb1,
                             const float* __restrict__ sw2, const float* __restrict__ sb2,
                             const float* __restrict__ lds,
                             float* __restrict__ out, int rows)
{
    __shared__ float hs[8][128];
    const int warp = threadIdx.x >> 5, lane = threadIdx.x & 31;
    const int node = blockIdx.x * 8 + warp;
    float disp = 0.001f + log1pf(expf(*lds));
    if (blockIdx.x == 0 && threadIdx.x == 0) out[5 * NN] = disp;
    if (node >= rows) return;

    float4 hv = ((const float4*)h)[(size_t)node * 32 + lane];
    ((float4*)hs[warp])[lane] = hv;
    __syncwarp();

    float d0 = db1[lane], d1 = db1[lane + 32];
    float s0 = sb1[lane], s1 = sb1[lane + 32];
#pragma unroll 4
    for (int k = 0; k < 128; k++) {
        float xv = hs[warp][k];
        d0 = fmaf(xv, __ldg(&dw1[k * 64 + lane]),      d0);
        d1 = fmaf(xv, __ldg(&dw1[k * 64 + lane + 32]), d1);
        s0 = fmaf(xv, __ldg(&sw1[k * 64 + lane]),      s0);
        s1 = fmaf(xv, __ldg(&sw1[k * 64 + lane + 32]), s1);
    }
    d0 = fmaxf(d0, 0.f); d1 = fmaxf(d1, 0.f);
    s0 = fmaxf(s0, 0.f); s1 = fmaxf(s1, 0.f);

    float p0 = d0 * dw2[lane * 3 + 0] + d1 * dw2[(lane + 32) * 3 + 0];
    float p1 = d0 * dw2[lane * 3 + 1] + d1 * dw2[(lane + 32) * 3 + 1];
    float p2 = d0 * dw2[lane * 3 + 2] + d1 * dw2[(lane + 32) * 3 + 2];
    float ps = s0 * sw2[lane] + s1 * sw2[lane + 32];
    p0 = wsum(p0); p1 = wsum(p1); p2 = wsum(p2); ps = wsum(ps);

    if (lane == 0) {
        float ls = ps + sb2[0];
        ls = fminf(fmaxf(ls, 0.f), 30.f);
        float s = expf(ls);
        out[node * 3 + 0] = (p0 + db2[0]) * disp;
        out[node * 3 + 1] = (p1 + db2[1]) * disp;
        out[node * 3 + 2] = (p2 + db2[2]) * disp;
        out[3 * NN + node] = s;
        out[4 * NN + node] = ls;
        out[5 * NN + 1 + node] = 2.5e8f / (s + 1e-8f);
    }
}

// ============================================================================
extern "C" void kernel_launch(void* const* d_in, const int* in_sizes, int n_in,
                              void* d_out, int out_size)
{
    const float* x     = (const float*)d_in[0];
    const float* eattr = (const float*)d_in[1];
    const int*   ei    = (const int*)  d_in[2];
    const float* ne_w1 = (const float*)d_in[3];
    const float* ne_b1 = (const float*)d_in[4];
    const float* ne_w2 = (const float*)d_in[5];
    const float* ne_b2 = (const float*)d_in[6];
    const float* ne_g  = (const float*)d_in[7];
    const float* ne_be = (const float*)d_in[8];
    const float* ee_w1 = (const float*)d_in[9];
    const float* ee_b1 = (const float*)d_in[10];
    const float* ee_w2 = (const float*)d_in[11];
    const float* ee_b2 = (const float*)d_in[12];
    const float* ee_g  = (const float*)d_in[13];
    const float* ee_be = (const float*)d_in[14];
    const float* cw1   = (const float*)d_in[15];
    const float* cb1   = (const float*)d_in[16];
    const float* cw2   = (const float*)d_in[17];
    const float* cb2   = (const float*)d_in[18];
    const float* pn_g  = (const float*)d_in[19];
    const float* pn_be = (const float*)d_in[20];
    const float* dw1   = (const float*)d_in[21];
    const float* db1   = (const float*)d_in[22];
    const float* dw2   = (const float*)d_in[23];
    const float* db2   = (const float*)d_in[24];
    const float* sw1   = (const float*)d_in[25];
    const float* sb1   = (const float*)d_in[26];
    const float* sw2   = (const float*)d_in[27];
    const float* sb2   = (const float*)d_in[28];
    const float* ldsc  = (const float*)d_in[29];
    float* out = (float*)d_out;

    void *ph, *phh, *pa, *pt, *pe, *pd, *ps, *pc, *px, *py;
    cudaGetSymbolAddress(&ph,  g_h);
    cudaGetSymbolAddress(&phh, g_hh);
    cudaGetSymbolAddress(&pa,  g_agg);
    cudaGetSymbolAddress(&pt,  g_t);
    cudaGetSymbolAddress(&pe,  g_ea);
    cudaGetSymbolAddress(&pd,  g_deg);
    cudaGetSymbolAddress(&ps,  g_start);
    cudaGetSymbolAddress(&pc,  g_cursor);
    cudaGetSymbolAddress(&px,  g_eidx);
    cudaGetSymbolAddress(&py,  g_esrc);
    float*  hbuf = (float*)ph;
    __half* hhb  = (__half*)phh;
    float*  abuf = (float*)pa;
    float*  tbuf = (float*)pt;
    __half* ebuf = (__half*)pe;
    int* deg    = (int*)pd;
    int* startb = (int*)ps;
    int* cursor = (int*)pc;
    int* eidx   = (int*)px;
    int* esrc   = (int*)py;

    const int gsm = SMEM_WORDS * 4;   // 104448 bytes
    cudaFuncSetAttribute(gemm128_kernel<5, 0, 2>, cudaFuncAttributeMaxDynamicSharedMemorySize, gsm);
    cudaFuncSetAttribute(gemm128_kernel<6, 0, 1>, cudaFuncAttributeMaxDynamicSharedMemorySize, gsm);
    cudaFuncSetAttribute(gemm128_kernel<0, 1, 0>, cudaFuncAttributeMaxDynamicSharedMemorySize, gsm);
    cudaFuncSetAttribute(gemm128_kernel<0, 2, 2>, cudaFuncAttributeMaxDynamicSharedMemorySize, gsm);

    // ---- CSR build (launches 1-3), then edge encoder as launch #4 (profiled)
    zero_kernel<<<(NN + 255) / 256, 256>>>(deg);
    hist_kernel<<<(EE + 255) / 256, 256>>>(ei, deg);
    scan_kernel<<<1, 1024>>>(deg, startb, cursor);

    // edge encoder: ea = fp16(LN(mlp2(edge_attr)))   [launch #4 -> ncu capture]
    gemm128_kernel<6, 0, 1><<<296, 256, gsm>>>(eattr, EE, ee_w2, ee_b2, ee_w1, ee_b1,
                                               ee_g, ee_be, nullptr, (float*)ebuf, nullptr);
    // node encoder: h = LN(mlp2(x)), hh = fp16(h)
    gemm128_kernel<5, 0, 2><<<296, 256, gsm>>>(x, NN, ne_w2, ne_b2, ne_w1, ne_b1,
                                               ne_g, ne_be, nullptr, hbuf, hhb);
    scatter_kernel<<<(EE + 255) / 256, 256>>>(ei, cursor, eidx, esrc);

    for (int l = 0; l < 3; l++) {
        gather_kernel<<<(NN + 7) / 8, 256>>>(startb, eidx, esrc, hbuf, hhb, ebuf, abuf);
        // t = relu(agg @ w1 + b1)
        gemm128_kernel<0, 1, 0><<<296, 256, gsm>>>(abuf, NN, cw1 + (size_t)l * 16384, cb1 + l * 128,
                                                   nullptr, nullptr, nullptr, nullptr, nullptr,
                                                   tbuf, nullptr);
        // h = LN(h + relu(t @ w2 + b2)), hh = fp16(h)
        gemm128_kernel<0, 2, 2><<<296, 256, gsm>>>(tbuf, NN, cw2 + (size_t)l * 16384, cb2 + l * 128,
                                                   nullptr, nullptr, pn_g + l * 128, pn_be + l * 128,
                                                   hbuf, hbuf, hhb);
    }
    heads_kernel<<<(NN + 7) / 8, 256>>>(hbuf, dw1, db1, dw2, db2,
                                        sw1, sb1, sw2, sb2, ldsc, out, NN);
}

// round 14
// speedup vs baseline: 1.0970x; 1.0070x over previous
#include <cuda_runtime.h>
#include <cuda_fp16.h>
#include <cstdint>

#define NN 50000
#define EE 600000

// ---------------- scratch ---------------------------------------------------
__device__ float  g_h  [(size_t)NN * 128];
__device__ __half g_hh [(size_t)NN * 128];   // fp16 shadow of h (12.8 MB)
__device__ float  g_agg[(size_t)NN * 128];
__device__ float  g_t  [(size_t)NN * 128];
__device__ __half g_ea [(size_t)EE * 128];   // fp16 edge features (154 MB)
// CSR scratch
__device__ int g_deg   [NN];
__device__ int g_start [NN + 1];
__device__ int g_cursor[NN];
__device__ int g_eidx  [EE];
__device__ int g_esrc  [EE];

// ---------------- helpers ----------------------------------------------------
// split (x0,x1) into packed bf16x2 hi and lo words: x ~= hi + lo, err ~2^-17
__device__ __forceinline__ void split2(float x0, float x1, uint32_t& hi, uint32_t& lo) {
    asm("cvt.rn.bf16x2.f32 %0, %2, %1;" : "=r"(hi) : "f"(x0), "f"(x1));
    float h0 = __uint_as_float(hi << 16);
    float h1 = __uint_as_float(hi & 0xffff0000u);
    float l0 = x0 - h0, l1 = x1 - h1;
    asm("cvt.rn.bf16x2.f32 %0, %2, %1;" : "=r"(lo) : "f"(l0), "f"(l1));
}
__device__ __forceinline__ void mma_bf16(float* d,
                                         uint32_t a0, uint32_t a1, uint32_t a2, uint32_t a3,
                                         uint32_t b0, uint32_t b1) {
    asm volatile("mma.sync.aligned.m16n8k16.row.col.f32.bf16.bf16.f32 "
        "{%0,%1,%2,%3}, {%4,%5,%6,%7}, {%8,%9}, {%0,%1,%2,%3};"
        : "+f"(d[0]), "+f"(d[1]), "+f"(d[2]), "+f"(d[3])
        : "r"(a0), "r"(a1), "r"(a2), "r"(a3), "r"(b0), "r"(b1));
}
__device__ __forceinline__ float wsum(float v) {
#pragma unroll
    for (int o = 16; o > 0; o >>= 1) v += __shfl_xor_sync(0xffffffffu, v, o);
    return v;
}
// load 4 consecutive fp16 (8 B) -> float4
__device__ __forceinline__ float4 ld_h4(const __half* p) {
    uint2 u = __ldg((const uint2*)p);
    __half2 h0 = *reinterpret_cast<__half2*>(&u.x);
    __half2 h1 = *reinterpret_cast<__half2*>(&u.y);
    float2 f0 = __half22float2(h0);
    float2 f1 = __half22float2(h1);
    return make_float4(f0.x, f0.y, f1.x, f1.y);
}

// SMEM word strides
#define KS2 68     // packed-k2 row stride

// word offsets inside dynamic smem (uint32 units); tile M = 64
#define OFF_AHI 0
#define OFF_ALO (64 * KS2)
#define OFF_BHI (2 * 64 * KS2)
#define OFF_BLO (2 * 64 * KS2 + 128 * KS2)
#define SMEM_WORDS (2 * 64 * KS2 + 2 * 128 * KS2)   // 26112 words = 104448 B

// ============================================================================
// Fused GEMM (out = f(A[rows,128] @ W[128,128])) via mma.sync bf16-split.
// Persistent CTAs; 64x128 tile per CTA; 8 warps; warp tile 32x32; 2 CTAs/SM.
// Software-pipelined mainloop: full unroll over 8 k-steps, double-buffered A
// fragments, B loads hoisted ahead of the MMA block.
// MODE 0: A = relu(x[KIN] @ w1 + b1) computed SIMT; epi: LN(D + b)
// MODE 1: A from gmem;                              epi: relu(D + b)
// MODE 2: A from gmem;                              epi: LN(hres + relu(D + b))
// OUTH 0: fp32 out1.  OUTH 1: fp16 only (out1 is __half*).  OUTH 2: fp32 + fp16.
// ============================================================================
template <int KIN, int MODE, int OUTH>
__global__ __launch_bounds__(256, 2)
void gemm128_kernel(const float* __restrict__ A, int rows,
                    const float* __restrict__ W, const float* __restrict__ bias,
                    const float* __restrict__ w1, const float* __restrict__ b1,
                    const float* __restrict__ gam, const float* __restrict__ bet,
                    const float* __restrict__ hres,
                    float* __restrict__ out1,
                    __half* __restrict__ outh)
{
    extern __shared__ uint32_t dyn[];
    uint32_t* Ahi = dyn + OFF_AHI;
    uint32_t* Alo = dyn + OFF_ALO;
    uint32_t* Bhi = dyn + OFF_BHI;
    uint32_t* Blo = dyn + OFF_BLO;
    __shared__ float w1s[KIN > 0 ? KIN * 128 : 1];
    __shared__ float b1s[128], bs[128], gs[128], bes[128];
    __shared__ float partial[64][9];   // [row][0..3]=sum per warp-col, [4..7]=sumsq

    const int tid  = threadIdx.x;
    const int lane = tid & 31;
    const int wrp  = tid >> 5;
    const int wm   = (wrp & 1) * 32;   // warp row offset (tile M=64)
    const int wn   = (wrp >> 1) * 32;  // warp col offset (4 groups)
    const int wc   = wn >> 5;          // warp-col index 0..3
    const int g    = lane >> 2;
    const int t4   = lane & 3;

    // ---- stage B = W (K-major) as packed bf16x2 hi/lo: Bs[n][k2] ----------
#pragma unroll
    for (int q = 0; q < 32; q++) {
        int i  = q * 256 + tid;
        int n  = i & 127, k2 = i >> 7;
        float v0 = W[(2 * k2) * 128 + n];
        float v1 = W[(2 * k2 + 1) * 128 + n];
        uint32_t h, l; split2(v0, v1, h, l);
        Bhi[n * KS2 + k2] = h;
        Blo[n * KS2 + k2] = l;
    }
    if (KIN > 0) {
        for (int i = tid; i < KIN * 128; i += 256) w1s[i] = w1[i];
        if (tid < 128) b1s[tid] = b1[tid];
    }
    if (tid < 128) {
        bs[tid] = bias[tid];
        if (MODE != 1) { gs[tid] = gam[tid]; bes[tid] = bet[tid]; }
    }
    __syncthreads();

    const int ntiles = (rows + 63) >> 6;
    for (int t = blockIdx.x; t < ntiles; t += gridDim.x) {
        const int row0 = t << 6;

        // ---------------- stage A tile (packed bf16x2 hi/lo) ----------------
        if (KIN > 0) {
            const int r = tid >> 2, p = tid & 3, rw = row0 + r;
            float xr[KIN > 0 ? KIN : 1];
#pragma unroll
            for (int j = 0; j < KIN; j++)
                xr[j] = (rw < rows) ? A[(size_t)rw * KIN + j] : 0.f;
#pragma unroll
            for (int j = 0; j < 16; j++) {
                int k2 = 4 * j + p;
                int c  = 2 * k2;
                float a0 = b1s[c], a1 = b1s[c + 1];
#pragma unroll
                for (int k = 0; k < KIN; k++) {
                    a0 = fmaf(xr[k], w1s[k * 128 + c], a0);
                    a1 = fmaf(xr[k], w1s[k * 128 + c + 1], a1);
                }
                a0 = fmaxf(a0, 0.f); a1 = fmaxf(a1, 0.f);
                uint32_t h, l; split2(a0, a1, h, l);
                Ahi[r * KS2 + k2] = h;
                Alo[r * KS2 + k2] = l;
            }
        } else {
#pragma unroll
            for (int q = 0; q < 16; q++) {
                int i  = q * 256 + tid;
                int r  = i >> 6, k2 = i & 63;
                float2 v = (row0 + r < rows)
                    ? *(const float2*)(A + (size_t)(row0 + r) * 128 + 2 * k2)
                    : make_float2(0.f, 0.f);
                uint32_t h, l; split2(v.x, v.y, h, l);
                Ahi[r * KS2 + k2] = h;
                Alo[r * KS2 + k2] = l;
            }
        }
        __syncthreads();

        // ---------------- mainloop: software-pipelined, full unroll ----------
        float d[2][4][4];
#pragma unroll
        for (int mt = 0; mt < 2; mt++)
#pragma unroll
            for (int nt = 0; nt < 4; nt++)
#pragma unroll
                for (int i = 0; i < 4; i++) d[mt][nt][i] = 0.f;

        uint32_t ah[2][2][4], al[2][2][4];   // [buf][mt][frag]

#define LOAD_A(KSV, BUF)                                                     \
        {                                                                    \
            const int kb_ = (KSV) * 8 + t4;                                  \
            _Pragma("unroll")                                                \
            for (int mt = 0; mt < 2; mt++) {                                 \
                const int rb = (wm + mt * 16 + g) * KS2 + kb_;               \
                ah[BUF][mt][0] = Ahi[rb];                                    \
                ah[BUF][mt][1] = Ahi[rb + 8 * KS2];                          \
                ah[BUF][mt][2] = Ahi[rb + 4];                                \
                ah[BUF][mt][3] = Ahi[rb + 8 * KS2 + 4];                      \
                al[BUF][mt][0] = Alo[rb];                                    \
                al[BUF][mt][1] = Alo[rb + 8 * KS2];                          \
                al[BUF][mt][2] = Alo[rb + 4];                                \
                al[BUF][mt][3] = Alo[rb + 8 * KS2 + 4];                      \
            }                                                                \
        }

        LOAD_A(0, 0);
#pragma unroll
        for (int ks = 0; ks < 8; ks++) {
            const int cur = ks & 1, nxt = cur ^ 1;
            const int kb = ks * 8 + t4;
            // hoist all B loads for this k-step
            uint32_t bh[4][2], bl[4][2];
#pragma unroll
            for (int nt = 0; nt < 4; nt++) {
                const int nb = (wn + nt * 8 + g) * KS2 + kb;
                bh[nt][0] = Bhi[nb]; bh[nt][1] = Bhi[nb + 4];
                bl[nt][0] = Blo[nb]; bl[nt][1] = Blo[nb + 4];
            }
            // prefetch next k-step's A fragments
            if (ks < 7) LOAD_A(ks + 1, nxt);
            // MMAs on current fragments (independent of in-flight loads)
#pragma unroll
            for (int nt = 0; nt < 4; nt++)
#pragma unroll
                for (int mt = 0; mt < 2; mt++) {
                    mma_bf16(d[mt][nt], ah[cur][mt][0], ah[cur][mt][1],
                             ah[cur][mt][2], ah[cur][mt][3], bh[nt][0], bh[nt][1]);
                    mma_bf16(d[mt][nt], al[cur][mt][0], al[cur][mt][1],
                             al[cur][mt][2], al[cur][mt][3], bh[nt][0], bh[nt][1]);
                    mma_bf16(d[mt][nt], ah[cur][mt][0], ah[cur][mt][1],
                             ah[cur][mt][2], ah[cur][mt][3], bl[nt][0], bl[nt][1]);
                }
        }
#undef LOAD_A

        // ---------------- epilogue: fragment-direct ----------------
        if (MODE == 1) {
#pragma unroll
            for (int mt = 0; mt < 2; mt++) {
#pragma unroll
                for (int h = 0; h < 2; h++) {
                    const int rl = wm + mt * 16 + g + 8 * h;
                    const int rw = row0 + rl;
                    if (rw < rows) {
#pragma unroll
                        for (int nt = 0; nt < 4; nt++) {
                            const int cb = wn + nt * 8 + 2 * t4;
                            float2 b = *(const float2*)&bs[cb];
                            float2 o;
                            o.x = fmaxf(d[mt][nt][2 * h]     + b.x, 0.f);
                            o.y = fmaxf(d[mt][nt][2 * h + 1] + b.y, 0.f);
                            *(float2*)(out1 + (size_t)rw * 128 + cb) = o;
                        }
                    }
                }
            }
        } else {
            // pass 1: bias(/relu/residual) in regs, per-row partial sums
#pragma unroll
            for (int mt = 0; mt < 2; mt++) {
#pragma unroll
                for (int h = 0; h < 2; h++) {
                    const int rl = wm + mt * 16 + g + 8 * h;
                    const int rw = row0 + rl;
                    const bool valid = rw < rows;
                    float sum = 0.f, sq = 0.f;
#pragma unroll
                    for (int nt = 0; nt < 4; nt++) {
                        const int cb = wn + nt * 8 + 2 * t4;
                        float2 b = *(const float2*)&bs[cb];
                        float w0 = d[mt][nt][2 * h]     + b.x;
                        float w1v = d[mt][nt][2 * h + 1] + b.y;
                        if (MODE == 2) {
                            float2 hv = valid ? *(const float2*)(hres + (size_t)rw * 128 + cb)
                                              : make_float2(0.f, 0.f);
                            w0  = hv.x + fmaxf(w0, 0.f);
                            w1v = hv.y + fmaxf(w1v, 0.f);
                        }
                        d[mt][nt][2 * h]     = w0;
                        d[mt][nt][2 * h + 1] = w1v;
                        sum += w0 + w1v;
                        sq  += w0 * w0 + w1v * w1v;
                    }
                    sum += __shfl_xor_sync(0xffffffffu, sum, 1);
                    sq  += __shfl_xor_sync(0xffffffffu, sq, 1);
                    sum += __shfl_xor_sync(0xffffffffu, sum, 2);
                    sq  += __shfl_xor_sync(0xffffffffu, sq, 2);
                    if (t4 == 0) {
                        partial[rl][wc]     = sum;
                        partial[rl][4 + wc] = sq;
                    }
                }
            }
            __syncthreads();
            // pass 2: combine 4 warp-col partials, normalize, store
#pragma unroll
            for (int mt = 0; mt < 2; mt++) {
#pragma unroll
                for (int h = 0; h < 2; h++) {
                    const int rl = wm + mt * 16 + g + 8 * h;
                    const int rw = row0 + rl;
                    float sum = partial[rl][0] + partial[rl][1] + partial[rl][2] + partial[rl][3];
                    float sq  = partial[rl][4] + partial[rl][5] + partial[rl][6] + partial[rl][7];
                    float mean = sum * 0.0078125f;
                    float var  = sq * 0.0078125f - mean * mean;
                    float inv  = rsqrtf(var + 1e-5f);
                    if (rw < rows) {
#pragma unroll
                        for (int nt = 0; nt < 4; nt++) {
                            const int cb = wn + nt * 8 + 2 * t4;
                            float2 gv = *(const float2*)&gs[cb];
                            float2 bv = *(const float2*)&bes[cb];
                            float ox = (d[mt][nt][2 * h]     - mean) * inv * gv.x + bv.x;
                            float oy = (d[mt][nt][2 * h + 1] - mean) * inv * gv.y + bv.y;
                            if (OUTH == 1) {
                                *(__half2*)((__half*)out1 + (size_t)rw * 128 + cb) =
                                    __floats2half2_rn(ox, oy);
                            } else {
                                *(float2*)(out1 + (size_t)rw * 128 + cb) = make_float2(ox, oy);
                                if (OUTH == 2)
                                    *(__half2*)(outh + (size_t)rw * 128 + cb) =
                                        __floats2half2_rn(ox, oy);
                            }
                        }
                    }
                }
            }
        }
        __syncthreads();  // smem (A region + partial) reused next tile
    }
}

// ============================================================================
// CSR build: zero -> histogram -> scan -> scatter
// ============================================================================
__global__ void zero_kernel(int* __restrict__ deg) {
    int i = blockIdx.x * blockDim.x + threadIdx.x;
    if (i < NN) deg[i] = 0;
}
__global__ void hist_kernel(const int* __restrict__ ei, int* __restrict__ deg) {
    int e = blockIdx.x * blockDim.x + threadIdx.x;
    if (e < EE) atomicAdd(&deg[ei[EE + e]], 1);
}
__global__ __launch_bounds__(1024, 1)
void scan_kernel(const int* __restrict__ deg, int* __restrict__ start,
                 int* __restrict__ cursor) {
    __shared__ int sums[1024];
    const int t = threadIdx.x;
    const int CH = (NN + 1023) / 1024;
    const int lo = t * CH;
    const int hi = (lo + CH < NN) ? lo + CH : NN;
    int s = 0;
    for (int i = lo; i < hi; i++) s += deg[i];
    sums[t] = s;
    __syncthreads();
    for (int o = 1; o < 1024; o <<= 1) {
        int u = (t >= o) ? sums[t - o] : 0;
        __syncthreads();
        sums[t] += u;
        __syncthreads();
    }
    int running = sums[t] - s;
    for (int i = lo; i < hi; i++) {
        start[i]  = running;
        cursor[i] = running;
        running += deg[i];
    }
    if (t == 1023) start[NN] = sums[1023];
}
__global__ void scatter_kernel(const int* __restrict__ ei, int* __restrict__ cursor,
                               int* __restrict__ eidx, int* __restrict__ esrc) {
    int e = blockIdx.x * blockDim.x + threadIdx.x;
    if (e >= EE) return;
    int dst = ei[EE + e];
    int pos = atomicAdd(&cursor[dst], 1);
    eidx[pos] = e;
    esrc[pos] = ei[e];
}

// ============================================================================
// Aggregation (gather): agg[n] = h[n] + sum_{e: dst=n} relu(hh[src_e] + ea[e])
// warp per node, lane = 4-feature chunk (8B fp16 loads); lane-parallel index
// fetch + shfl, unroll 4.  (R13 version — equal-best, lowest traffic.)
// ============================================================================
__global__ __launch_bounds__(256, 4)
void gather_kernel(const int* __restrict__ start,
                   const int* __restrict__ eidx, const int* __restrict__ esrc,
                   const float* __restrict__ h, const __half* __restrict__ hh,
                   const __half* __restrict__ ea, float* __restrict__ agg)
{
    const int warp = threadIdx.x >> 5, lane = threadIdx.x & 31;
    const int node = blockIdx.x * 8 + warp;
    if (node >= NN) return;
    const int s   = __ldg(&start[node]);
    const int deg = __ldg(&start[node + 1]) - s;

    float4 acc = __ldg((const float4*)h + (size_t)node * 32 + lane);

    for (int base = 0; base < deg; base += 32) {
        int rem = deg - base; if (rem > 32) rem = 32;
        int ie = 0, is_ = 0;
        if (lane < rem) {
            ie  = __ldg(&eidx[s + base + lane]);
            is_ = __ldg(&esrc[s + base + lane]);
        }
        int j = 0;
        for (; j + 4 <= rem; j += 4) {
            int e0 = __shfl_sync(0xffffffffu, ie, j);
            int e1 = __shfl_sync(0xffffffffu, ie, j + 1);
            int e2 = __shfl_sync(0xffffffffu, ie, j + 2);
            int e3 = __shfl_sync(0xffffffffu, ie, j + 3);
            int s0 = __shfl_sync(0xffffffffu, is_, j);
            int s1 = __shfl_sync(0xffffffffu, is_, j + 1);
            int s2 = __shfl_sync(0xffffffffu, is_, j + 2);
            int s3 = __shfl_sync(0xffffffffu, is_, j + 3);
            float4 ev0 = ld_h4(ea + (size_t)e0 * 128 + lane * 4);
            float4 ev1 = ld_h4(ea + (size_t)e1 * 128 + lane * 4);
            float4 ev2 = ld_h4(ea + (size_t)e2 * 128 + lane * 4);
            float4 ev3 = ld_h4(ea + (size_t)e3 * 128 + lane * 4);
            float4 hv0 = ld_h4(hh + (size_t)s0 * 128 + lane * 4);
            float4 hv1 = ld_h4(hh + (size_t)s1 * 128 + lane * 4);
            float4 hv2 = ld_h4(hh + (size_t)s2 * 128 + lane * 4);
            float4 hv3 = ld_h4(hh + (size_t)s3 * 128 + lane * 4);
            acc.x += fmaxf(hv0.x + ev0.x, 0.f) + fmaxf(hv1.x + ev1.x, 0.f)
                   + fmaxf(hv2.x + ev2.x, 0.f) + fmaxf(hv3.x + ev3.x, 0.f);
            acc.y += fmaxf(hv0.y + ev0.y, 0.f) + fmaxf(hv1.y + ev1.y, 0.f)
                   + fmaxf(hv2.y + ev2.y, 0.f) + fmaxf(hv3.y + ev3.y, 0.f);
            acc.z += fmaxf(hv0.z + ev0.z, 0.f) + fmaxf(hv1.z + ev1.z, 0.f)
                   + fmaxf(hv2.z + ev2.z, 0.f) + fmaxf(hv3.z + ev3.z, 0.f);
            acc.w += fmaxf(hv0.w + ev0.w, 0.f) + fmaxf(hv1.w + ev1.w, 0.f)
                   + fmaxf(hv2.w + ev2.w, 0.f) + fmaxf(hv3.w + ev3.w, 0.f);
        }
        for (; j < rem; j++) {
            int e0 = __shfl_sync(0xffffffffu, ie, j);
            int s0 = __shfl_sync(0xffffffffu, is_, j);
            float4 ev0 = ld_h4(ea + (size_t)e0 * 128 + lane * 4);
            float4 hv0 = ld_h4(hh + (size_t)s0 * 128 + lane * 4);
            acc.x += fmaxf(hv0.x + ev0.x, 0.f);
            acc.y += fmaxf(hv0.y + ev0.y, 0.f);
            acc.z += fmaxf(hv0.z + ev0.z, 0.f);
            acc.w += fmaxf(hv0.w + ev0.w, 0.f);
        }
    }
    ((float4*)agg)[(size_t)node * 32 + lane] = acc;
}

// ============================================================================
// Heads: one warp per node. Output: u[3N] | s[N] | log_s[N] | disp[1] | safety[N]
// ============================================================================
__global__ void heads_kernel(const float* __restrict__ h,
                             const float* __restrict__ dw1, const float* __restrict__ db1,
                             const float* __restrict__ dw2, const float* __restrict__ db2,
                             const float* __restrict__ sw1, const float* __restrict__ sb1,
                             const float* __restrict__ sw2, const float* __restrict__ sb2,
                             const float* __restrict__ lds,
                             float* __restrict__ out, int rows)
{
    __shared__ float hs[8][128];
    const int warp = threadIdx.x >> 5, lane = threadIdx.x & 31;
    const int node = blockIdx.x * 8 + warp;
    float disp = 0.001f + log1pf(expf(*lds));
    if (blockIdx.x == 0 && threadIdx.x == 0) out[5 * NN] = disp;
    if (node >= rows) return;

    float4 hv = ((const float4*)h)[(size_t)node * 32 + lane];
    ((float4*)hs[warp])[lane] = hv;
    __syncwarp();

    float d0 = db1[lane], d1 = db1[lane + 32];
    float s0 = sb1[lane], s1 = sb1[lane + 32];
#pragma unroll 4
    for (int k = 0; k < 128; k++) {
        float xv = hs[warp][k];
        d0 = fmaf(xv, __ldg(&dw1[k * 64 + lane]),      d0);
        d1 = fmaf(xv, __ldg(&dw1[k * 64 + lane + 32]), d1);
        s0 = fmaf(xv, __ldg(&sw1[k * 64 + lane]),      s0);
        s1 = fmaf(xv, __ldg(&sw1[k * 64 + lane + 32]), s1);
    }
    d0 = fmaxf(d0, 0.f); d1 = fmaxf(d1, 0.f);
    s0 = fmaxf(s0, 0.f); s1 = fmaxf(s1, 0.f);

    float p0 = d0 * dw2[lane * 3 + 0] + d1 * dw2[(lane + 32) * 3 + 0];
    float p1 = d0 * dw2[lane * 3 + 1] + d1 * dw2[(lane + 32) * 3 + 1];
    float p2 = d0 * dw2[lane * 3 + 2] + d1 * dw2[(lane + 32) * 3 + 2];
    float ps = s0 * sw2[lane] + s1 * sw2[lane + 32];
    p0 = wsum(p0); p1 = wsum(p1); p2 = wsum(p2); ps = wsum(ps);

    if (lane == 0) {
        float ls = ps + sb2[0];
        ls = fminf(fmaxf(ls, 0.f), 30.f);
        float s = expf(ls);
        out[node * 3 + 0] = (p0 + db2[0]) * disp;
        out[node * 3 + 1] = (p1 + db2[1]) * disp;
        out[node * 3 + 2] = (p2 + db2[2]) * disp;
        out[3 * NN + node] = s;
        out[4 * NN + node] = ls;
        out[5 * NN + 1 + node] = 2.5e8f / (s + 1e-8f);
    }
}

// ============================================================================
extern "C" void kernel_launch(void* const* d_in, const int* in_sizes, int n_in,
                              void* d_out, int out_size)
{
    const float* x     = (const float*)d_in[0];
    const float* eattr = (const float*)d_in[1];
    const int*   ei    = (const int*)  d_in[2];
    const float* ne_w1 = (const float*)d_in[3];
    const float* ne_b1 = (const float*)d_in[4];
    const float* ne_w2 = (const float*)d_in[5];
    const float* ne_b2 = (const float*)d_in[6];
    const float* ne_g  = (const float*)d_in[7];
    const float* ne_be = (const float*)d_in[8];
    const float* ee_w1 = (const float*)d_in[9];
    const float* ee_b1 = (const float*)d_in[10];
    const float* ee_w2 = (const float*)d_in[11];
    const float* ee_b2 = (const float*)d_in[12];
    const float* ee_g  = (const float*)d_in[13];
    const float* ee_be = (const float*)d_in[14];
    const float* cw1   = (const float*)d_in[15];
    const float* cb1   = (const float*)d_in[16];
    const float* cw2   = (const float*)d_in[17];
    const float* cb2   = (const float*)d_in[18];
    const float* pn_g  = (const float*)d_in[19];
    const float* pn_be = (const float*)d_in[20];
    const float* dw1   = (const float*)d_in[21];
    const float* db1   = (const float*)d_in[22];
    const float* dw2   = (const float*)d_in[23];
    const float* db2   = (const float*)d_in[24];
    const float* sw1   = (const float*)d_in[25];
    const float* sb1   = (const float*)d_in[26];
    const float* sw2   = (const float*)d_in[27];
    const float* sb2   = (const float*)d_in[28];
    const float* ldsc  = (const float*)d_in[29];
    float* out = (float*)d_out;

    void *ph, *phh, *pa, *pt, *pe, *pd, *ps, *pc, *px, *py;
    cudaGetSymbolAddress(&ph,  g_h);
    cudaGetSymbolAddress(&phh, g_hh);
    cudaGetSymbolAddress(&pa,  g_agg);
    cudaGetSymbolAddress(&pt,  g_t);
    cudaGetSymbolAddress(&pe,  g_ea);
    cudaGetSymbolAddress(&pd,  g_deg);
    cudaGetSymbolAddress(&ps,  g_start);
    cudaGetSymbolAddress(&pc,  g_cursor);
    cudaGetSymbolAddress(&px,  g_eidx);
    cudaGetSymbolAddress(&py,  g_esrc);
    float*  hbuf = (float*)ph;
    __half* hhb  = (__half*)phh;
    float*  abuf = (float*)pa;
    float*  tbuf = (float*)pt;
    __half* ebuf = (__half*)pe;
    int* deg    = (int*)pd;
    int* startb = (int*)ps;
    int* cursor = (int*)pc;
    int* eidx   = (int*)px;
    int* esrc   = (int*)py;

    const int gsm = SMEM_WORDS * 4;   // 104448 bytes
    cudaFuncSetAttribute(gemm128_kernel<5, 0, 2>, cudaFuncAttributeMaxDynamicSharedMemorySize, gsm);
    cudaFuncSetAttribute(gemm128_kernel<6, 0, 1>, cudaFuncAttributeMaxDynamicSharedMemorySize, gsm);
    cudaFuncSetAttribute(gemm128_kernel<0, 1, 0>, cudaFuncAttributeMaxDynamicSharedMemorySize, gsm);
    cudaFuncSetAttribute(gemm128_kernel<0, 2, 2>, cudaFuncAttributeMaxDynamicSharedMemorySize, gsm);

    // ---- CSR build (launches 1-3), then edge encoder as launch #4 (profiled)
    zero_kernel<<<(NN + 255) / 256, 256>>>(deg);
    hist_kernel<<<(EE + 255) / 256, 256>>>(ei, deg);
    scan_kernel<<<1, 1024>>>(deg, startb, cursor);

    // edge encoder: ea = fp16(LN(mlp2(edge_attr)))   [launch #4 -> ncu capture]
    gemm128_kernel<6, 0, 1><<<296, 256, gsm>>>(eattr, EE, ee_w2, ee_b2, ee_w1, ee_b1,
                                               ee_g, ee_be, nullptr, (float*)ebuf, nullptr);
    // node encoder: h = LN(mlp2(x)), hh = fp16(h)
    gemm128_kernel<5, 0, 2><<<296, 256, gsm>>>(x, NN, ne_w2, ne_b2, ne_w1, ne_b1,
                                               ne_g, ne_be, nullptr, hbuf, hhb);
    scatter_kernel<<<(EE + 255) / 256, 256>>>(ei, cursor, eidx, esrc);

    for (int l = 0; l < 3; l++) {
        gather_kernel<<<(NN + 7) / 8, 256>>>(startb, eidx, esrc, hbuf, hhb, ebuf, abuf);
        // t = relu(agg @ w1 + b1)
        gemm128_kernel<0, 1, 0><<<296, 256, gsm>>>(abuf, NN, cw1 + (size_t)l * 16384, cb1 + l * 128,
                                                   nullptr, nullptr, nullptr, nullptr, nullptr,
                                                   tbuf, nullptr);
        // h = LN(h + relu(t @ w2 + b2)), hh = fp16(h)
        gemm128_kernel<0, 2, 2><<<296, 256, gsm>>>(tbuf, NN, cw2 + (size_t)l * 16384, cb2 + l * 128,
                                                   nullptr, nullptr, pn_g + l * 128, pn_be + l * 128,
                                                   hbuf, hbuf, hhb);
    }
    heads_kernel<<<(NN + 7) / 8, 256>>>(hbuf, dw1, db1, dw2, db2,
                                        sw1, sb1, sw2, sb2, ldsc, out, NN);
}

// round 15
// speedup vs baseline: 1.0975x; 1.0005x over previous
#include <cuda_runtime.h>
#include <cuda_fp16.h>
#include <cstdint>

#define NN 50000
#define EE 600000

// ---------------- scratch ---------------------------------------------------
__device__ float  g_h  [(size_t)NN * 128];
__device__ __half g_hh [(size_t)NN * 128];
__device__ float  g_agg[(size_t)NN * 128];
__device__ float  g_t  [(size_t)NN * 128];
__device__ __half g_ea [(size_t)EE * 128];
// CSR scratch
__device__ int g_deg   [NN];
__device__ int g_start [NN + 1];
__device__ int g_cursor[NN];
__device__ int g_eidx  [EE];
__device__ int g_esrc  [EE];

// ---------------- helpers ----------------------------------------------------
__device__ __forceinline__ void split2(float x0, float x1, uint32_t& hi, uint32_t& lo) {
    asm("cvt.rn.bf16x2.f32 %0, %2, %1;" : "=r"(hi) : "f"(x0), "f"(x1));
    float h0 = __uint_as_float(hi << 16);
    float h1 = __uint_as_float(hi & 0xffff0000u);
    float l0 = x0 - h0, l1 = x1 - h1;
    asm("cvt.rn.bf16x2.f32 %0, %2, %1;" : "=r"(lo) : "f"(l0), "f"(l1));
}
__device__ __forceinline__ void mma_bf16(float* d,
                                         uint32_t a0, uint32_t a1, uint32_t a2, uint32_t a3,
                                         uint32_t b0, uint32_t b1) {
    asm volatile("mma.sync.aligned.m16n8k16.row.col.f32.bf16.bf16.f32 "
        "{%0,%1,%2,%3}, {%4,%5,%6,%7}, {%8,%9}, {%0,%1,%2,%3};"
        : "+f"(d[0]), "+f"(d[1]), "+f"(d[2]), "+f"(d[3])
        : "r"(a0), "r"(a1), "r"(a2), "r"(a3), "r"(b0), "r"(b1));
}
__device__ __forceinline__ float wsum(float v) {
#pragma unroll
    for (int o = 16; o > 0; o >>= 1) v += __shfl_xor_sync(0xffffffffu, v, o);
    return v;
}
__device__ __forceinline__ float4 ld_h4(const __half* p) {
    uint2 u = __ldg((const uint2*)p);
    __half2 h0 = *reinterpret_cast<__half2*>(&u.x);
    __half2 h1 = *reinterpret_cast<__half2*>(&u.y);
    float2 f0 = __half22float2(h0);
    float2 f1 = __half22float2(h1);
    return make_float4(f0.x, f0.y, f1.x, f1.y);
}

// SMEM word strides
#define KS2 68     // packed-k2 row stride

// word offsets inside dynamic smem (uint32 units); tile M = 64
#define OFF_AHI 0
#define OFF_ALO (64 * KS2)
#define OFF_BHI (2 * 64 * KS2)
#define OFF_BLO (2 * 64 * KS2 + 128 * KS2)
#define SMEM_WORDS (2 * 64 * KS2 + 2 * 128 * KS2)   // 26112 words = 104448 B

// ============================================================================
// Fused GEMM (out = f(A[rows,128] @ W[128,128])) via mma.sync bf16-split.
// Persistent CTAs; 64x128 tile per CTA; 8 warps; warp tile 32x32; 2 CTAs/SM.
// MODE 0 (KIN>0): layer-1 relu(x@w1+b1) computed via a single padded k16 MMA
//   (w1 pre-split into frag-layout smem; x frags loaded straight from gmem).
// MODE 1: A from gmem; epi: relu(D + b)
// MODE 2: A from gmem; epi: LN(hres + relu(D + b))
// OUTH 0: fp32 out1.  OUTH 1: fp16 only (out1 is __half*).  OUTH 2: fp32+fp16.
// LN epilogue 'partial' lives in the (dead) dynamic A region.
// ============================================================================
template <int KIN, int MODE, int OUTH>
__global__ __launch_bounds__(256, 2)
void gemm128_kernel(const float* __restrict__ A, int rows,
                    const float* __restrict__ W, const float* __restrict__ bias,
                    const float* __restrict__ w1, const float* __restrict__ b1,
                    const float* __restrict__ gam, const float* __restrict__ bet,
                    const float* __restrict__ hres,
                    float* __restrict__ out1,
                    __half* __restrict__ outh)
{
    extern __shared__ uint32_t dyn[];
    uint32_t* Ahi = dyn + OFF_AHI;
    uint32_t* Alo = dyn + OFF_ALO;
    uint32_t* Bhi = dyn + OFF_BHI;
    uint32_t* Blo = dyn + OFF_BLO;
    float*    partial = (float*)dyn;          // [64][9], reuses A region in epilogue
    __shared__ uint32_t w1f[KIN > 0 ? 2 * 128 * 8 : 1];  // w1 bf16 hi/lo frag layout
    __shared__ float b1s[KIN > 0 ? 128 : 1];
    __shared__ float bs[128], gs[128], bes[128];

    const int tid  = threadIdx.x;
    const int lane = tid & 31;
    const int wrp  = tid >> 5;
    const int wm   = (wrp & 1) * 32;   // warp row offset (tile M=64)
    const int wn   = (wrp >> 1) * 32;  // warp col offset
    const int wc   = wn >> 5;          // warp-col index 0..3
    const int g    = lane >> 2;
    const int t4   = lane & 3;

    // ---- stage B = W (K-major) as packed bf16x2 hi/lo: Bs[n][k2] ----------
#pragma unroll
    for (int q = 0; q < 32; q++) {
        int i  = q * 256 + tid;
        int n  = i & 127, k2 = i >> 7;
        float v0 = W[(2 * k2) * 128 + n];
        float v1 = W[(2 * k2 + 1) * 128 + n];
        uint32_t h, l; split2(v0, v1, h, l);
        Bhi[n * KS2 + k2] = h;
        Blo[n * KS2 + k2] = l;
    }
    if (KIN > 0) {
        // w1 [KIN,128] -> frag layout [n][k2] padded to k16, bf16 hi/lo
        for (int i = tid; i < 1024; i += 256) {
            int n = i >> 3, k2 = i & 7;
            float v0 = (2 * k2     < KIN) ? w1[(2 * k2) * 128 + n]     : 0.f;
            float v1 = (2 * k2 + 1 < KIN) ? w1[(2 * k2 + 1) * 128 + n] : 0.f;
            uint32_t h, l; split2(v0, v1, h, l);
            w1f[n * 8 + k2]        = h;
            w1f[1024 + n * 8 + k2] = l;
        }
        if (tid < 128) b1s[tid] = b1[tid];
    }
    if (tid < 128) {
        bs[tid] = bias[tid];
        if (MODE != 1) { gs[tid] = gam[tid]; bes[tid] = bet[tid]; }
    }
    __syncthreads();

    const int ntiles = (rows + 63) >> 6;
    for (int t = blockIdx.x; t < ntiles; t += gridDim.x) {
        const int row0 = t << 6;

        // ---------------- stage A tile (packed bf16x2 hi/lo) ----------------
        if (KIN > 0) {
            // layer-1 via MMA: x frags from gmem (upper k-half is zero pad)
            uint32_t xh[2][2], xl[2][2];
#pragma unroll
            for (int mt = 0; mt < 2; mt++)
#pragma unroll
                for (int hh = 0; hh < 2; hh++) {
                    int rw = row0 + wm + mt * 16 + hh * 8 + g;
                    float f0 = (rw < rows && 2 * t4     < KIN) ? __ldg(&A[(size_t)rw * KIN + 2 * t4])     : 0.f;
                    float f1 = (rw < rows && 2 * t4 + 1 < KIN) ? __ldg(&A[(size_t)rw * KIN + 2 * t4 + 1]) : 0.f;
                    split2(f0, f1, xh[mt][hh], xl[mt][hh]);
                }
            uint32_t w1h[4][2], w1l[4][2];
#pragma unroll
            for (int nt = 0; nt < 4; nt++) {
                int n0 = wn + nt * 8 + g;
                w1h[nt][0] = w1f[n0 * 8 + t4];
                w1h[nt][1] = w1f[n0 * 8 + t4 + 4];
                w1l[nt][0] = w1f[1024 + n0 * 8 + t4];
                w1l[nt][1] = w1f[1024 + n0 * 8 + t4 + 4];
            }
            float d1[2][4][4];
#pragma unroll
            for (int mt = 0; mt < 2; mt++)
#pragma unroll
                for (int nt = 0; nt < 4; nt++)
#pragma unroll
                    for (int i = 0; i < 4; i++) d1[mt][nt][i] = 0.f;
#pragma unroll
            for (int nt = 0; nt < 4; nt++)
#pragma unroll
                for (int mt = 0; mt < 2; mt++) {
                    mma_bf16(d1[mt][nt], xh[mt][0], xh[mt][1], 0u, 0u, w1h[nt][0], w1h[nt][1]);
                    mma_bf16(d1[mt][nt], xl[mt][0], xl[mt][1], 0u, 0u, w1h[nt][0], w1h[nt][1]);
                    mma_bf16(d1[mt][nt], xh[mt][0], xh[mt][1], 0u, 0u, w1l[nt][0], w1l[nt][1]);
                }
            // +b1, relu, split, store to Ahi/Alo (k2 = col/2)
#pragma unroll
            for (int mt = 0; mt < 2; mt++)
#pragma unroll
                for (int nt = 0; nt < 4; nt++) {
                    float2 bb = *(const float2*)&b1s[wn + nt * 8 + 2 * t4];
                    const int k2 = (wn >> 1) + nt * 4 + t4;
#pragma unroll
                    for (int hh = 0; hh < 2; hh++) {
                        const int rl = wm + mt * 16 + g + 8 * hh;
                        float v0 = fmaxf(d1[mt][nt][2 * hh]     + bb.x, 0.f);
                        float v1 = fmaxf(d1[mt][nt][2 * hh + 1] + bb.y, 0.f);
                        uint32_t h, l; split2(v0, v1, h, l);
                        Ahi[rl * KS2 + k2] = h;
                        Alo[rl * KS2 + k2] = l;
                    }
                }
        } else {
#pragma unroll
            for (int q = 0; q < 16; q++) {
                int i  = q * 256 + tid;
                int r  = i >> 6, k2 = i & 63;
                float2 v = (row0 + r < rows)
                    ? *(const float2*)(A + (size_t)(row0 + r) * 128 + 2 * k2)
                    : make_float2(0.f, 0.f);
                uint32_t h, l; split2(v.x, v.y, h, l);
                Ahi[r * KS2 + k2] = h;
                Alo[r * KS2 + k2] = l;
            }
        }
        __syncthreads();

        // ---------------- mainloop ----------------
        float d[2][4][4];
#pragma unroll
        for (int mt = 0; mt < 2; mt++)
#pragma unroll
            for (int nt = 0; nt < 4; nt++)
#pragma unroll
                for (int i = 0; i < 4; i++) d[mt][nt][i] = 0.f;

        if (KIN > 0) {
            // single-buffered (frees regs for the layer-1 frags above)
#pragma unroll 1
            for (int ks = 0; ks < 8; ks++) {
                const int kb = ks * 8 + t4;
                uint32_t ah[2][4], al[2][4];
#pragma unroll
                for (int mt = 0; mt < 2; mt++) {
                    const int rb = (wm + mt * 16 + g) * KS2 + kb;
                    ah[mt][0] = Ahi[rb];
                    ah[mt][1] = Ahi[rb + 8 * KS2];
                    ah[mt][2] = Ahi[rb + 4];
                    ah[mt][3] = Ahi[rb + 8 * KS2 + 4];
                    al[mt][0] = Alo[rb];
                    al[mt][1] = Alo[rb + 8 * KS2];
                    al[mt][2] = Alo[rb + 4];
                    al[mt][3] = Alo[rb + 8 * KS2 + 4];
                }
#pragma unroll
                for (int nt = 0; nt < 4; nt++) {
                    const int nb = (wn + nt * 8 + g) * KS2 + kb;
                    uint32_t bh0 = Bhi[nb], bh1 = Bhi[nb + 4];
                    uint32_t bl0 = Blo[nb], bl1 = Blo[nb + 4];
#pragma unroll
                    for (int mt = 0; mt < 2; mt++) {
                        mma_bf16(d[mt][nt], ah[mt][0], ah[mt][1], ah[mt][2], ah[mt][3], bh0, bh1);
                        mma_bf16(d[mt][nt], al[mt][0], al[mt][1], al[mt][2], al[mt][3], bh0, bh1);
                        mma_bf16(d[mt][nt], ah[mt][0], ah[mt][1], ah[mt][2], ah[mt][3], bl0, bl1);
                    }
                }
            }
        } else {
            // software-pipelined (R14)
            uint32_t ah[2][2][4], al[2][2][4];
#define LOAD_A(KSV, BUF)                                                     \
            {                                                                \
                const int kb_ = (KSV) * 8 + t4;                              \
                _Pragma("unroll")                                            \
                for (int mt = 0; mt < 2; mt++) {                             \
                    const int rb = (wm + mt * 16 + g) * KS2 + kb_;           \
                    ah[BUF][mt][0] = Ahi[rb];                                \
                    ah[BUF][mt][1] = Ahi[rb + 8 * KS2];                      \
                    ah[BUF][mt][2] = Ahi[rb + 4];                            \
                    ah[BUF][mt][3] = Ahi[rb + 8 * KS2 + 4];                  \
                    al[BUF][mt][0] = Alo[rb];                                \
                    al[BUF][mt][1] = Alo[rb + 8 * KS2];                      \
                    al[BUF][mt][2] = Alo[rb + 4];                            \
                    al[BUF][mt][3] = Alo[rb + 8 * KS2 + 4];                  \
                }                                                            \
            }
            LOAD_A(0, 0);
#pragma unroll
            for (int ks = 0; ks < 8; ks++) {
                const int cur = ks & 1, nxt = cur ^ 1;
                const int kb = ks * 8 + t4;
                uint32_t bh[4][2], bl[4][2];
#pragma unroll
                for (int nt = 0; nt < 4; nt++) {
                    const int nb = (wn + nt * 8 + g) * KS2 + kb;
                    bh[nt][0] = Bhi[nb]; bh[nt][1] = Bhi[nb + 4];
                    bl[nt][0] = Blo[nb]; bl[nt][1] = Blo[nb + 4];
                }
                if (ks < 7) LOAD_A(ks + 1, nxt);
#pragma unroll
                for (int nt = 0; nt < 4; nt++)
#pragma unroll
                    for (int mt = 0; mt < 2; mt++) {
                        mma_bf16(d[mt][nt], ah[cur][mt][0], ah[cur][mt][1],
                                 ah[cur][mt][2], ah[cur][mt][3], bh[nt][0], bh[nt][1]);
                        mma_bf16(d[mt][nt], al[cur][mt][0], al[cur][mt][1],
                                 al[cur][mt][2], al[cur][mt][3], bh[nt][0], bh[nt][1]);
                        mma_bf16(d[mt][nt], ah[cur][mt][0], ah[cur][mt][1],
                                 ah[cur][mt][2], ah[cur][mt][3], bl[nt][0], bl[nt][1]);
                    }
            }
#undef LOAD_A
        }
        __syncthreads();   // A region dead -> reused as partial[] below

        // ---------------- epilogue: fragment-direct ----------------
        if (MODE == 1) {
#pragma unroll
            for (int mt = 0; mt < 2; mt++) {
#pragma unroll
                for (int h = 0; h < 2; h++) {
                    const int rl = wm + mt * 16 + g + 8 * h;
                    const int rw = row0 + rl;
                    if (rw < rows) {
#pragma unroll
                        for (int nt = 0; nt < 4; nt++) {
                            const int cb = wn + nt * 8 + 2 * t4;
                            float2 b = *(const float2*)&bs[cb];
                            float2 o;
                            o.x = fmaxf(d[mt][nt][2 * h]     + b.x, 0.f);
                            o.y = fmaxf(d[mt][nt][2 * h + 1] + b.y, 0.f);
                            *(float2*)(out1 + (size_t)rw * 128 + cb) = o;
                        }
                    }
                }
            }
        } else {
#pragma unroll
            for (int mt = 0; mt < 2; mt++) {
#pragma unroll
                for (int h = 0; h < 2; h++) {
                    const int rl = wm + mt * 16 + g + 8 * h;
                    const int rw = row0 + rl;
                    const bool valid = rw < rows;
                    float sum = 0.f, sq = 0.f;
#pragma unroll
                    for (int nt = 0; nt < 4; nt++) {
                        const int cb = wn + nt * 8 + 2 * t4;
                        float2 b = *(const float2*)&bs[cb];
                        float w0 = d[mt][nt][2 * h]     + b.x;
                        float w1v = d[mt][nt][2 * h + 1] + b.y;
                        if (MODE == 2) {
                            float2 hv = valid ? *(const float2*)(hres + (size_t)rw * 128 + cb)
                                              : make_float2(0.f, 0.f);
                            w0  = hv.x + fmaxf(w0, 0.f);
                            w1v = hv.y + fmaxf(w1v, 0.f);
                        }
                        d[mt][nt][2 * h]     = w0;
                        d[mt][nt][2 * h + 1] = w1v;
                        sum += w0 + w1v;
                        sq  += w0 * w0 + w1v * w1v;
                    }
                    sum += __shfl_xor_sync(0xffffffffu, sum, 1);
                    sq  += __shfl_xor_sync(0xffffffffu, sq, 1);
                    sum += __shfl_xor_sync(0xffffffffu, sum, 2);
                    sq  += __shfl_xor_sync(0xffffffffu, sq, 2);
                    if (t4 == 0) {
                        partial[rl * 9 + wc]     = sum;
                        partial[rl * 9 + 4 + wc] = sq;
                    }
                }
            }
            __syncthreads();
#pragma unroll
            for (int mt = 0; mt < 2; mt++) {
#pragma unroll
                for (int h = 0; h < 2; h++) {
                    const int rl = wm + mt * 16 + g + 8 * h;
                    const int rw = row0 + rl;
                    float sum = partial[rl * 9 + 0] + partial[rl * 9 + 1]
                              + partial[rl * 9 + 2] + partial[rl * 9 + 3];
                    float sq  = partial[rl * 9 + 4] + partial[rl * 9 + 5]
                              + partial[rl * 9 + 6] + partial[rl * 9 + 7];
                    float mean = sum * 0.0078125f;
                    float var  = sq * 0.0078125f - mean * mean;
                    float inv  = rsqrtf(var + 1e-5f);
                    if (rw < rows) {
#pragma unroll
                        for (int nt = 0; nt < 4; nt++) {
                            const int cb = wn + nt * 8 + 2 * t4;
                            float2 gv = *(const float2*)&gs[cb];
                            float2 bv = *(const float2*)&bes[cb];
                            float ox = (d[mt][nt][2 * h]     - mean) * inv * gv.x + bv.x;
                            float oy = (d[mt][nt][2 * h + 1] - mean) * inv * gv.y + bv.y;
                            if (OUTH == 1) {
                                *(__half2*)((__half*)out1 + (size_t)rw * 128 + cb) =
                                    __floats2half2_rn(ox, oy);
                            } else {
                                *(float2*)(out1 + (size_t)rw * 128 + cb) = make_float2(ox, oy);
                                if (OUTH == 2)
                                    *(__half2*)(outh + (size_t)rw * 128 + cb) =
                                        __floats2half2_rn(ox, oy);
                            }
                        }
                    }
                }
            }
        }
        __syncthreads();  // smem reused next tile
    }
}

// ============================================================================
// CSR build: zero -> histogram -> scan -> scatter
// ============================================================================
__global__ void zero_kernel(int* __restrict__ deg) {
    int i = blockIdx.x * blockDim.x + threadIdx.x;
    if (i < NN) deg[i] = 0;
}
__global__ void hist_kernel(const int* __restrict__ ei, int* __restrict__ deg) {
    int e = blockIdx.x * blockDim.x + threadIdx.x;
    if (e < EE) atomicAdd(&deg[ei[EE + e]], 1);
}
__global__ __launch_bounds__(1024, 1)
void scan_kernel(const int* __restrict__ deg, int* __restrict__ start,
                 int* __restrict__ cursor) {
    __shared__ int sums[1024];
    const int t = threadIdx.x;
    const int CH = (NN + 1023) / 1024;
    const int lo = t * CH;
    const int hi = (lo + CH < NN) ? lo + CH : NN;
    int s = 0;
    for (int i = lo; i < hi; i++) s += deg[i];
    sums[t] = s;
    __syncthreads();
    for (int o = 1; o < 1024; o <<= 1) {
        int u = (t >= o) ? sums[t - o] : 0;
        __syncthreads();
        sums[t] += u;
        __syncthreads();
    }
    int running = sums[t] - s;
    for (int i = lo; i < hi; i++) {
        start[i]  = running;
        cursor[i] = running;
        running += deg[i];
    }
    if (t == 1023) start[NN] = sums[1023];
}
__global__ void scatter_kernel(const int* __restrict__ ei, int* __restrict__ cursor,
                               int* __restrict__ eidx, int* __restrict__ esrc) {
    int e = blockIdx.x * blockDim.x + threadIdx.x;
    if (e >= EE) return;
    int dst = ei[EE + e];
    int pos = atomicAdd(&cursor[dst], 1);
    eidx[pos] = e;
    esrc[pos] = ei[e];
}

// ============================================================================
// Aggregation (gather): agg[n] = h[n] + sum_{e: dst=n} relu(hh[src_e] + ea[e])
// ============================================================================
__global__ __launch_bounds__(256, 4)
void gather_kernel(const int* __restrict__ start,
                   const int* __restrict__ eidx, const int* __restrict__ esrc,
                   const float* __restrict__ h, const __half* __restrict__ hh,
                   const __half* __restrict__ ea, float* __restrict__ agg)
{
    const int warp = threadIdx.x >> 5, lane = threadIdx.x & 31;
    const int node = blockIdx.x * 8 + warp;
    if (node >= NN) return;
    const int s   = __ldg(&start[node]);
    const int deg = __ldg(&start[node + 1]) - s;

    float4 acc = __ldg((const float4*)h + (size_t)node * 32 + lane);

    for (int base = 0; base < deg; base += 32) {
        int rem = deg - base; if (rem > 32) rem = 32;
        int ie = 0, is_ = 0;
        if (lane < rem) {
            ie  = __ldg(&eidx[s + base + lane]);
            is_ = __ldg(&esrc[s + base + lane]);
        }
        int j = 0;
        for (; j + 4 <= rem; j += 4) {
            int e0 = __shfl_sync(0xffffffffu, ie, j);
            int e1 = __shfl_sync(0xffffffffu, ie, j + 1);
            int e2 = __shfl_sync(0xffffffffu, ie, j + 2);
            int e3 = __shfl_sync(0xffffffffu, ie, j + 3);
            int s0 = __shfl_sync(0xffffffffu, is_, j);
            int s1 = __shfl_sync(0xffffffffu, is_, j + 1);
            int s2 = __shfl_sync(0xffffffffu, is_, j + 2);
            int s3 = __shfl_sync(0xffffffffu, is_, j + 3);
            float4 ev0 = ld_h4(ea + (size_t)e0 * 128 + lane * 4);
            float4 ev1 = ld_h4(ea + (size_t)e1 * 128 + lane * 4);
            float4 ev2 = ld_h4(ea + (size_t)e2 * 128 + lane * 4);
            float4 ev3 = ld_h4(ea + (size_t)e3 * 128 + lane * 4);
            float4 hv0 = ld_h4(hh + (size_t)s0 * 128 + lane * 4);
            float4 hv1 = ld_h4(hh + (size_t)s1 * 128 + lane * 4);
            float4 hv2 = ld_h4(hh + (size_t)s2 * 128 + lane * 4);
            float4 hv3 = ld_h4(hh + (size_t)s3 * 128 + lane * 4);
            acc.x += fmaxf(hv0.x + ev0.x, 0.f) + fmaxf(hv1.x + ev1.x, 0.f)
                   + fmaxf(hv2.x + ev2.x, 0.f) + fmaxf(hv3.x + ev3.x, 0.f);
            acc.y += fmaxf(hv0.y + ev0.y, 0.f) + fmaxf(hv1.y + ev1.y, 0.f)
                   + fmaxf(hv2.y + ev2.y, 0.f) + fmaxf(hv3.y + ev3.y, 0.f);
            acc.z += fmaxf(hv0.z + ev0.z, 0.f) + fmaxf(hv1.z + ev1.z, 0.f)
                   + fmaxf(hv2.z + ev2.z, 0.f) + fmaxf(hv3.z + ev3.z, 0.f);
            acc.w += fmaxf(hv0.w + ev0.w, 0.f) + fmaxf(hv1.w + ev1.w, 0.f)
                   + fmaxf(hv2.w + ev2.w, 0.f) + fmaxf(hv3.w + ev3.w, 0.f);
        }
        for (; j < rem; j++) {
            int e0 = __shfl_sync(0xffffffffu, ie, j);
            int s0 = __shfl_sync(0xffffffffu, is_, j);
            float4 ev0 = ld_h4(ea + (size_t)e0 * 128 + lane * 4);
            float4 hv0 = ld_h4(hh + (size_t)s0 * 128 + lane * 4);
            acc.x += fmaxf(hv0.x + ev0.x, 0.f);
            acc.y += fmaxf(hv0.y + ev0.y, 0.f);
            acc.z += fmaxf(hv0.z + ev0.z, 0.f);
            acc.w += fmaxf(hv0.w + ev0.w, 0.f);
        }
    }
    ((float4*)agg)[(size_t)node * 32 + lane] = acc;
}

// ============================================================================
// Heads: one warp per node. Output: u[3N] | s[N] | log_s[N] | disp[1] | safety[N]
// ============================================================================
__global__ void heads_kernel(const float* __restrict__ h,
                             const float* __restrict__ dw1, const float* __restrict__ db1,
                             const float* __restrict__ dw2, const float* __restrict__ db2,
                             const float* __restrict__ sw1, const float* __restrict__ sb1,
                             const float* __restrict__ sw2, const float* __restrict__ sb2,
                             const float* __restrict__ lds,
                             float* __restrict__ out, int rows)
{
    __shared__ float hs[8][128];
    const int warp = threadIdx.x >> 5, lane = threadIdx.x & 31;
    const int node = blockIdx.x * 8 + warp;
    float disp = 0.001f + log1pf(expf(*lds));
    if (blockIdx.x == 0 && threadIdx.x == 0) out[5 * NN] = disp;
    if (node >= rows) return;

    float4 hv = ((const float4*)h)[(size_t)node * 32 + lane];
    ((float4*)hs[warp])[lane] = hv;
    __syncwarp();

    float d0 = db1[lane], d1 = db1[lane + 32];
    float s0 = sb1[lane], s1 = sb1[lane + 32];
#pragma unroll 4
    for (int k = 0; k < 128; k++) {
        float xv = hs[warp][k];
        d0 = fmaf(xv, __ldg(&dw1[k * 64 + lane]),      d0);
        d1 = fmaf(xv, __ldg(&dw1[k * 64 + lane + 32]), d1);
        s0 = fmaf(xv, __ldg(&sw1[k * 64 + lane]),      s0);
        s1 = fmaf(xv, __ldg(&sw1[k * 64 + lane + 32]), s1);
    }
    d0 = fmaxf(d0, 0.f); d1 = fmaxf(d1, 0.f);
    s0 = fmaxf(s0, 0.f); s1 = fmaxf(s1, 0.f);

    float p0 = d0 * dw2[lane * 3 + 0] + d1 * dw2[(lane + 32) * 3 + 0];
    float p1 = d0 * dw2[lane * 3 + 1] + d1 * dw2[(lane + 32) * 3 + 1];
    float p2 = d0 * dw2[lane * 3 + 2] + d1 * dw2[(lane + 32) * 3 + 2];
    float ps = s0 * sw2[lane] + s1 * sw2[lane + 32];
    p0 = wsum(p0); p1 = wsum(p1); p2 = wsum(p2); ps = wsum(ps);

    if (lane == 0) {
        float ls = ps + sb2[0];
        ls = fminf(fmaxf(ls, 0.f), 30.f);
        float s = expf(ls);
        out[node * 3 + 0] = (p0 + db2[0]) * disp;
        out[node * 3 + 1] = (p1 + db2[1]) * disp;
        out[node * 3 + 2] = (p2 + db2[2]) * disp;
        out[3 * NN + node] = s;
        out[4 * NN + node] = ls;
        out[5 * NN + 1 + node] = 2.5e8f / (s + 1e-8f);
    }
}

// ============================================================================
extern "C" void kernel_launch(void* const* d_in, const int* in_sizes, int n_in,
                              void* d_out, int out_size)
{
    const float* x     = (const float*)d_in[0];
    const float* eattr = (const float*)d_in[1];
    const int*   ei    = (const int*)  d_in[2];
    const float* ne_w1 = (const float*)d_in[3];
    const float* ne_b1 = (const float*)d_in[4];
    const float* ne_w2 = (const float*)d_in[5];
    const float* ne_b2 = (const float*)d_in[6];
    const float* ne_g  = (const float*)d_in[7];
    const float* ne_be = (const float*)d_in[8];
    const float* ee_w1 = (const float*)d_in[9];
    const float* ee_b1 = (const float*)d_in[10];
    const float* ee_w2 = (const float*)d_in[11];
    const float* ee_b2 = (const float*)d_in[12];
    const float* ee_g  = (const float*)d_in[13];
    const float* ee_be = (const float*)d_in[14];
    const float* cw1   = (const float*)d_in[15];
    const float* cb1   = (const float*)d_in[16];
    const float* cw2   = (const float*)d_in[17];
    const float* cb2   = (const float*)d_in[18];
    const float* pn_g  = (const float*)d_in[19];
    const float* pn_be = (const float*)d_in[20];
    const float* dw1   = (const float*)d_in[21];
    const float* db1   = (const float*)d_in[22];
    const float* dw2   = (const float*)d_in[23];
    const float* db2   = (const float*)d_in[24];
    const float* sw1   = (const float*)d_in[25];
    const float* sb1   = (const float*)d_in[26];
    const float* sw2   = (const float*)d_in[27];
    const float* sb2   = (const float*)d_in[28];
    const float* ldsc  = (const float*)d_in[29];
    float* out = (float*)d_out;

    void *ph, *phh, *pa, *pt, *pe, *pd, *ps, *pc, *px, *py;
    cudaGetSymbolAddress(&ph,  g_h);
    cudaGetSymbolAddress(&phh, g_hh);
    cudaGetSymbolAddress(&pa,  g_agg);
    cudaGetSymbolAddress(&pt,  g_t);
    cudaGetSymbolAddress(&pe,  g_ea);
    cudaGetSymbolAddress(&pd,  g_deg);
    cudaGetSymbolAddress(&ps,  g_start);
    cudaGetSymbolAddress(&pc,  g_cursor);
    cudaGetSymbolAddress(&px,  g_eidx);
    cudaGetSymbolAddress(&py,  g_esrc);
    float*  hbuf = (float*)ph;
    __half* hhb  = (__half*)phh;
    float*  abuf = (float*)pa;
    float*  tbuf = (float*)pt;
    __half* ebuf = (__half*)pe;
    int* deg    = (int*)pd;
    int* startb = (int*)ps;
    int* cursor = (int*)pc;
    int* eidx   = (int*)px;
    int* esrc   = (int*)py;

    const int gsm = SMEM_WORDS * 4;   // 104448 bytes
    cudaFuncSetAttribute(gemm128_kernel<5, 0, 2>, cudaFuncAttributeMaxDynamicSharedMemorySize, gsm);
    cudaFuncSetAttribute(gemm128_kernel<6, 0, 1>, cudaFuncAttributeMaxDynamicSharedMemorySize, gsm);
    cudaFuncSetAttribute(gemm128_kernel<0, 1, 0>, cudaFuncAttributeMaxDynamicSharedMemorySize, gsm);
    cudaFuncSetAttribute(gemm128_kernel<0, 2, 2>, cudaFuncAttributeMaxDynamicSharedMemorySize, gsm);

    // ---- CSR build (launches 1-3), then edge encoder as launch #4 (profiled)
    zero_kernel<<<(NN + 255) / 256, 256>>>(deg);
    hist_kernel<<<(EE + 255) / 256, 256>>>(ei, deg);
    scan_kernel<<<1, 1024>>>(deg, startb, cursor);

    // edge encoder: ea = fp16(LN(mlp2(edge_attr)))   [launch #4 -> ncu capture]
    gemm128_kernel<6, 0, 1><<<296, 256, gsm>>>(eattr, EE, ee_w2, ee_b2, ee_w1, ee_b1,
                                               ee_g, ee_be, nullptr, (float*)ebuf, nullptr);
    // node encoder: h = LN(mlp2(x)), hh = fp16(h)
    gemm128_kernel<5, 0, 2><<<296, 256, gsm>>>(x, NN, ne_w2, ne_b2, ne_w1, ne_b1,
                                               ne_g, ne_be, nullptr, hbuf, hhb);
    scatter_kernel<<<(EE + 255) / 256, 256>>>(ei, cursor, eidx, esrc);

    for (int l = 0; l < 3; l++) {
        gather_kernel<<<(NN + 7) / 8, 256>>>(startb, eidx, esrc, hbuf, hhb, ebuf, abuf);
        // t = relu(agg @ w1 + b1)
        gemm128_kernel<0, 1, 0><<<296, 256, gsm>>>(abuf, NN, cw1 + (size_t)l * 16384, cb1 + l * 128,
                                                   nullptr, nullptr, nullptr, nullptr, nullptr,
                                                   tbuf, nullptr);
        // h = LN(h + relu(t @ w2 + b2)), hh = fp16(h)
        gemm128_kernel<0, 2, 2><<<296, 256, gsm>>>(tbuf, NN, cw2 + (size_t)l * 16384, cb2 + l * 128,
                                                   nullptr, nullptr, pn_g + l * 128, pn_be + l * 128,
                                                   hbuf, hbuf, hhb);
    }
    heads_kernel<<<(NN + 7) / 8, 256>>>(hbuf, dw1, db1, dw2, db2,
                                        sw1, sb1, sw2, sb2, ldsc, out, NN);
}